// round 10
// baseline (speedup 1.0000x reference)
#include <cuda_runtime.h>
#include <cuda_bf16.h>
#include <cstdint>

// ---------------------------------------------------------------------------
// MambaBlock on GB300 (plain sm_103 -> mma.sync path).
// in/out_proj: bf16-split 3-pass mma.sync m16n8k16 (R8-proven 256-thread,
// 64x32-warp config), cp.async double buffering; out_proj split-K=2.
// Scan: float4-vectorized loads from transposed xdblT.
// ---------------------------------------------------------------------------

#define NTOK    2048
#define DMODEL  1024
#define DINNER  2048
#define DSTATE  16
#define DTRANK  64
#define XDBL_N  96
#define SPLITK  8

__device__ float g_xt  [DINNER * NTOK];
__device__ float g_zt  [DINNER * NTOK];
__device__ float g_xct [DINNER * NTOK];
__device__ float g_dtt [DINNER * NTOK];
__device__ float g_yt  [NTOK * DINNER];          // token-major
__device__ float g_xdblT[XDBL_N * NTOK];         // TRANSPOSED x_proj out
__device__ float g_xdbl_part[SPLITK * NTOK * XDBL_N];
__device__ float g_opart[2 * NTOK * DMODEL];

// pre-split bf16 hi/lo buffers
__device__ __nv_bfloat16 g_h_hi [NTOK * DMODEL];
__device__ __nv_bfloat16 g_h_lo [NTOK * DMODEL];
__device__ __nv_bfloat16 g_iw_hi[2 * DINNER * DMODEL];
__device__ __nv_bfloat16 g_iw_lo[2 * DINNER * DMODEL];
__device__ __nv_bfloat16 g_yt_hi[NTOK * DINNER];
__device__ __nv_bfloat16 g_yt_lo[NTOK * DINNER];
__device__ __nv_bfloat16 g_ow_hi[DMODEL * DINNER];
__device__ __nv_bfloat16 g_ow_lo[DMODEL * DINNER];

// =========================== helpers =======================================
__device__ __forceinline__ uint32_t smem_u32(const void* p) {
    uint32_t a;
    asm("{ .reg .u64 t; cvta.to.shared.u64 t, %1; cvt.u32.u64 %0, t; }"
        : "=r"(a) : "l"(p));
    return a;
}

__device__ __forceinline__ void ldm_x4(uint32_t* r, uint32_t addr) {
    asm volatile("ldmatrix.sync.aligned.m8n8.x4.shared.b16 {%0,%1,%2,%3}, [%4];"
        : "=r"(r[0]), "=r"(r[1]), "=r"(r[2]), "=r"(r[3]) : "r"(addr));
}

__device__ __forceinline__ void mma_bf16(float* c, const uint32_t* a,
                                         const uint32_t* b) {
    asm volatile(
        "mma.sync.aligned.m16n8k16.row.col.f32.bf16.bf16.f32 "
        "{%0,%1,%2,%3}, {%4,%5,%6,%7}, {%8,%9}, {%0,%1,%2,%3};"
        : "+f"(c[0]), "+f"(c[1]), "+f"(c[2]), "+f"(c[3])
        : "r"(a[0]), "r"(a[1]), "r"(a[2]), "r"(a[3]), "r"(b[0]), "r"(b[1]));
}

#define CP16(dst, src) \
    asm volatile("cp.async.cg.shared.global [%0], [%1], 16;" \
                 :: "r"(dst), "l"(src))
#define CP_COMMIT() asm volatile("cp.async.commit_group;" ::: "memory")

// fp32 -> bf16 hi/lo split (elementwise)
__global__ void __launch_bounds__(256) cvt_split(
    const float* __restrict__ src, __nv_bfloat16* __restrict__ hi,
    __nv_bfloat16* __restrict__ lo, int n4)
{
    const int i = blockIdx.x * 256 + threadIdx.x;
    if (i >= n4) return;
    const float4 v = reinterpret_cast<const float4*>(src)[i];
    __nv_bfloat162 h0 = __floats2bfloat162_rn(v.x, v.y);
    __nv_bfloat162 h1 = __floats2bfloat162_rn(v.z, v.w);
    __nv_bfloat162 l0 = __floats2bfloat162_rn(v.x - __bfloat162float(h0.x),
                                              v.y - __bfloat162float(h0.y));
    __nv_bfloat162 l1 = __floats2bfloat162_rn(v.z - __bfloat162float(h1.x),
                                              v.w - __bfloat162float(h1.y));
    reinterpret_cast<__nv_bfloat162*>(hi)[2*i]   = h0;
    reinterpret_cast<__nv_bfloat162*>(hi)[2*i+1] = h1;
    reinterpret_cast<__nv_bfloat162*>(lo)[2*i]   = l0;
    reinterpret_cast<__nv_bfloat162*>(lo)[2*i+1] = l1;
}

// ---------------------------------------------------------------------------
// bf16-split tensor GEMM (R8 config): CTA 128x128, 256 threads, 8 warps =
// 2(m) x 4(n), warp 64x32, Kc=32/stage, double-buffered cp.async.
// TMODE 0: channel-major store via smem transpose; n<2048 -> out0 else out1.
// TMODE 1: split-K partial: out0[z*2048*1024 + m*1024 + n] = D.
// Stage (bytes): Ahi[128][40]b16 @0, Alo @10240, Bhi @20480, Blo @30720.
// ---------------------------------------------------------------------------
#define KC 32
#define STG    40960
#define R_A_LO 10240
#define R_B_HI 20480
#define R_B_LO 30720
#define MM_SMEM 81920

template<int TMODE>
__global__ void __launch_bounds__(256, 2) mm_gemm(
    const __nv_bfloat16* __restrict__ Ahi, const __nv_bfloat16* __restrict__ Alo,
    int lda,
    const __nv_bfloat16* __restrict__ Bhi, const __nv_bfloat16* __restrict__ Blo,
    int ldb, int nchunk,
    float* __restrict__ out0, float* __restrict__ out1)
{
    extern __shared__ char smem_dyn[];
    const uint32_t sbase = smem_u32(smem_dyn);
    const int tid  = threadIdx.x;
    const int lane = tid & 31;
    const int w    = tid >> 5;
    const int wm   = w >> 2;             // 0..1
    const int wn   = w & 3;              // 0..3
    const int n0   = blockIdx.x * 128;
    const int m0   = blockIdx.y * 128;
    const int kbase = blockIdx.z * nchunk;

    const int lrow  = tid >> 1;          // 0..127
    const int lhalf = (tid & 1) * 16;    // elements

    const int a_row  = wm * 64 + (lane & 15);
    const int a_coff = ((lane & 16) ? 16 : 0);
    const int b_row  = wn * 32 + ((lane >> 4) & 1) * 8 + (lane & 7);
    const int b_coff = ((lane & 8) ? 16 : 0);

    float acc[4][4][4];
    #pragma unroll
    for (int i = 0; i < 4; i++)
        #pragma unroll
        for (int j = 0; j < 4; j++)
            #pragma unroll
            for (int p = 0; p < 4; p++) acc[i][j][p] = 0.f;

#define ISSUE(gc_, buf_) do {                                                   \
    const int kc0 = (gc_) * KC;                                                 \
    const uint32_t sd = sbase + (buf_) * STG + lrow * 80 + lhalf * 2;           \
    const __nv_bfloat16* a0 = Ahi + (size_t)(m0 + lrow) * lda + kc0 + lhalf;    \
    const __nv_bfloat16* a1 = Alo + (size_t)(m0 + lrow) * lda + kc0 + lhalf;    \
    const __nv_bfloat16* b0 = Bhi + (size_t)(n0 + lrow) * ldb + kc0 + lhalf;    \
    const __nv_bfloat16* b1 = Blo + (size_t)(n0 + lrow) * ldb + kc0 + lhalf;    \
    CP16(sd,               a0);  CP16(sd + 16,          a0 + 8);                \
    CP16(sd + R_A_LO,      a1);  CP16(sd + R_A_LO + 16, a1 + 8);                \
    CP16(sd + R_B_HI,      b0);  CP16(sd + R_B_HI + 16, b0 + 8);                \
    CP16(sd + R_B_LO,      b1);  CP16(sd + R_B_LO + 16, b1 + 8);                \
    CP_COMMIT();                                                                \
    } while (0)

#define COMPUTE(buf_) do {                                                      \
    const uint32_t sa = sbase + (buf_) * STG;                                   \
    _Pragma("unroll")                                                           \
    for (int s = 0; s < 2; s++) {                                               \
        uint32_t Ah[4][4], Al[4][4], Bh[2][4], Bl[2][4];                        \
        _Pragma("unroll")                                                       \
        for (int mf = 0; mf < 4; mf++) {                                        \
            const uint32_t ar = sa + (a_row + mf * 16) * 80 + a_coff + s * 32;  \
            ldm_x4(Ah[mf], ar);                                                 \
            ldm_x4(Al[mf], ar + R_A_LO);                                        \
        }                                                                       \
        _Pragma("unroll")                                                       \
        for (int np = 0; np < 2; np++) {                                        \
            const uint32_t br = sa + R_B_HI + (b_row + np * 16) * 80            \
                                + b_coff + s * 32;                              \
            ldm_x4(Bh[np], br);                                                 \
            ldm_x4(Bl[np], br + (R_B_LO - R_B_HI));                             \
        }                                                                       \
        _Pragma("unroll")                                                       \
        for (int mf = 0; mf < 4; mf++)                                          \
            _Pragma("unroll")                                                   \
            for (int nf = 0; nf < 4; nf++) {                                    \
                const uint32_t* bh = &Bh[nf >> 1][(nf & 1) * 2];                \
                const uint32_t* bl = &Bl[nf >> 1][(nf & 1) * 2];                \
                mma_bf16(acc[mf][nf], Ah[mf], bh);                              \
                mma_bf16(acc[mf][nf], Ah[mf], bl);                              \
                mma_bf16(acc[mf][nf], Al[mf], bh);                              \
            }                                                                   \
    } } while (0)

    ISSUE(kbase, 0);
    for (int c = 0; c < nchunk; c++) {
        const int buf = c & 1;
        if (c + 1 < nchunk) {
            ISSUE(kbase + c + 1, buf ^ 1);
            asm volatile("cp.async.wait_group 1;" ::: "memory");
        } else {
            asm volatile("cp.async.wait_group 0;" ::: "memory");
        }
        __syncthreads();
        COMPUTE(buf);
        __syncthreads();
    }

#undef ISSUE
#undef COMPUTE

    const int rg = lane >> 2;
    const int cp = (lane & 3) * 2;

    if (TMODE == 0) {
        float* T = reinterpret_cast<float*>(smem_dyn);
        #pragma unroll
        for (int mf = 0; mf < 4; mf++)
            #pragma unroll
            for (int nf = 0; nf < 4; nf++) {
                const int m = wm * 64 + mf * 16 + rg;
                const int n = wn * 32 + nf * 8 + cp;
                T[(n    ) * 132 + m    ] = acc[mf][nf][0];
                T[(n + 1) * 132 + m    ] = acc[mf][nf][1];
                T[(n    ) * 132 + m + 8] = acc[mf][nf][2];
                T[(n + 1) * 132 + m + 8] = acc[mf][nf][3];
            }
        __syncthreads();
        float* ob; int nc0;
        if (n0 < 2048) { ob = out0; nc0 = n0; }
        else           { ob = out1; nc0 = n0 - 2048; }
        const int n  = tid >> 1;
        const int mh = (tid & 1) * 64;
        const float4* src = reinterpret_cast<const float4*>(&T[n * 132 + mh]);
        float4* dst = reinterpret_cast<float4*>(
            ob + (size_t)(nc0 + n) * NTOK + m0 + mh);
        #pragma unroll
        for (int j = 0; j < 16; j++) dst[j] = src[j];
    } else {
        float* part = out0 + (size_t)blockIdx.z * NTOK * DMODEL;
        #pragma unroll
        for (int mf = 0; mf < 4; mf++)
            #pragma unroll
            for (int nf = 0; nf < 4; nf++) {
                const int m = m0 + wm * 64 + mf * 16 + rg;
                const int n = n0 + wn * 32 + nf * 8 + cp;
                *reinterpret_cast<float2*>(part + (size_t)m * DMODEL + n) =
                    make_float2(acc[mf][nf][0], acc[mf][nf][1]);
                *reinterpret_cast<float2*>(part + (size_t)(m + 8) * DMODEL + n) =
                    make_float2(acc[mf][nf][2], acc[mf][nf][3]);
            }
    }
}

// out = part0 + part1 + x
__global__ void __launch_bounds__(256) add_out(
    const float* __restrict__ part, const float* __restrict__ x,
    float* __restrict__ out)
{
    const int i = blockIdx.x * 256 + threadIdx.x;
    const float4 a = reinterpret_cast<const float4*>(part)[i];
    const float4 b = reinterpret_cast<const float4*>(part + NTOK * DMODEL)[i];
    const float4 c = reinterpret_cast<const float4*>(x)[i];
    float4 o;
    o.x = a.x + b.x + c.x; o.y = a.y + b.y + c.y;
    o.z = a.z + b.z + c.z; o.w = a.w + b.w + c.w;
    reinterpret_cast<float4*>(out)[i] = o;
}

// ============================ fp32 kernels =================================
__device__ __forceinline__ unsigned long long dup2(float x) {
    unsigned long long r;
    asm("mov.b64 %0, {%1, %1};" : "=l"(r) : "f"(x));
    return r;
}
__device__ __forceinline__ void fma2(unsigned long long& d,
                                     unsigned long long a,
                                     unsigned long long b) {
    asm("fma.rn.f32x2 %0, %1, %2, %0;" : "+l"(d) : "l"(a), "l"(b));
}

// LayerNorm -> bf16 hi/lo
__global__ void __launch_bounds__(256) ln_kernel(
    const float* __restrict__ x, const float* __restrict__ w,
    const float* __restrict__ b,
    __nv_bfloat16* __restrict__ hi, __nv_bfloat16* __restrict__ lo)
{
    const int t = blockIdx.x;
    const float4 v = reinterpret_cast<const float4*>(x + (size_t)t * DMODEL)[threadIdx.x];
    float s  = v.x + v.y + v.z + v.w;
    float sq = v.x*v.x + v.y*v.y + v.z*v.z + v.w*v.w;

    __shared__ float sa[8], sb2[8];
    int lane = threadIdx.x & 31, wrp = threadIdx.x >> 5;
    #pragma unroll
    for (int o = 16; o; o >>= 1) {
        s  += __shfl_down_sync(0xffffffffu, s,  o);
        sq += __shfl_down_sync(0xffffffffu, sq, o);
    }
    if (lane == 0) { sa[wrp] = s; sb2[wrp] = sq; }
    __syncthreads();
    if (wrp == 0) {
        s  = (lane < 8) ? sa[lane] : 0.f;
        sq = (lane < 8) ? sb2[lane] : 0.f;
        #pragma unroll
        for (int o = 4; o; o >>= 1) {
            s  += __shfl_down_sync(0xffffffffu, s,  o);
            sq += __shfl_down_sync(0xffffffffu, sq, o);
        }
        if (lane == 0) { sa[0] = s; sb2[0] = sq; }
    }
    __syncthreads();
    const float mu  = sa[0] * (1.f / DMODEL);
    const float var = sb2[0] * (1.f / DMODEL) - mu * mu;
    const float inv = rsqrtf(var + 1e-5f);

    const float4 wv = reinterpret_cast<const float4*>(w)[threadIdx.x];
    const float4 bv = reinterpret_cast<const float4*>(b)[threadIdx.x];
    float4 o4;
    o4.x = (v.x - mu) * inv * wv.x + bv.x;
    o4.y = (v.y - mu) * inv * wv.y + bv.y;
    o4.z = (v.z - mu) * inv * wv.z + bv.z;
    o4.w = (v.w - mu) * inv * wv.w + bv.w;

    __nv_bfloat162 h0 = __floats2bfloat162_rn(o4.x, o4.y);
    __nv_bfloat162 h1 = __floats2bfloat162_rn(o4.z, o4.w);
    __nv_bfloat162 l0 = __floats2bfloat162_rn(o4.x - __bfloat162float(h0.x),
                                              o4.y - __bfloat162float(h0.y));
    __nv_bfloat162 l1 = __floats2bfloat162_rn(o4.z - __bfloat162float(h1.x),
                                              o4.w - __bfloat162float(h1.y));
    const size_t base2 = ((size_t)t * DMODEL) / 2 + threadIdx.x * 2;
    reinterpret_cast<__nv_bfloat162*>(hi)[base2]     = h0;
    reinterpret_cast<__nv_bfloat162*>(hi)[base2 + 1] = h1;
    reinterpret_cast<__nv_bfloat162*>(lo)[base2]     = l0;
    reinterpret_cast<__nv_bfloat162*>(lo)[base2 + 1] = l1;
}

#define BM  128
#define BKT 16
#define APAD 4

template<int MODE, bool ACOL, int TN>
__global__ void __launch_bounds__(256) gemm_k(
    const float* __restrict__ A, int lda, const float* __restrict__ B,
    float* __restrict__ C, float* __restrict__ C2,
    const float* __restrict__ bias, const float* __restrict__ resid,
    int M, int N, int K, int kSplitLen)
{
    constexpr int BN = TN * 16;
    __shared__ __align__(16) float As[2][BKT][BM + APAD];
    __shared__ __align__(16) float Bs[2][BKT][BN];

    const int tid = threadIdx.x;
    const int n0 = blockIdx.x * BN;
    const int m0 = blockIdx.y * BM;
    const int kBase = blockIdx.z * kSplitLen;
    const int nT = kSplitLen / BKT;
    const int tm = tid >> 4, tn = tid & 15;

    unsigned long long acc[TN][4];
    #pragma unroll
    for (int j = 0; j < TN; j++)
        #pragma unroll
        for (int p = 0; p < 4; p++) acc[j][p] = 0ull;

    float4 ar0, ar1, br0, br1;

#define LOAD_A(k0_) do {                                                        \
    if (ACOL) {                                                                 \
        const int m4 = tid & 31, kr = tid >> 5;                                 \
        ar0 = *(const float4*)(A + (size_t)((k0_) + kr)     * lda + m0 + m4*4); \
        ar1 = *(const float4*)(A + (size_t)((k0_) + kr + 8) * lda + m0 + m4*4); \
    } else {                                                                    \
        const int rr = tid >> 2, kq = tid & 3;                                  \
        ar0 = *(const float4*)(A + (size_t)(m0 + rr)      * lda + (k0_) + kq*4);\
        ar1 = *(const float4*)(A + (size_t)(m0 + rr + 64) * lda + (k0_) + kq*4);\
    } } while (0)

#define LOAD_B(k0_) do {                                                        \
    if (TN == 8) {                                                              \
        const int nr = tid >> 1, kq = tid & 1;                                  \
        if (n0 + nr < N) {                                                      \
            const float* bp = B + (size_t)(n0 + nr) * K + (k0_) + kq * 8;       \
            br0 = *(const float4*)(bp);                                         \
            br1 = *(const float4*)(bp + 4);                                     \
        } else { br0 = make_float4(0,0,0,0); br1 = br0; }                       \
    } else {                                                                    \
        const int nr = tid >> 2, kq = tid & 3;                                  \
        br0 = (n0 + nr < N)                                                     \
            ? *(const float4*)(B + (size_t)(n0 + nr) * K + (k0_) + kq*4)        \
            : make_float4(0,0,0,0);                                             \
    } } while (0)

#define STORE_A(st_) do {                                                       \
    if (ACOL) {                                                                 \
        const int m4 = tid & 31, kr = tid >> 5;                                 \
        *(float4*)&As[st_][kr  ][m4*4] = ar0;                                   \
        *(float4*)&As[st_][kr+8][m4*4] = ar1;                                   \
    } else {                                                                    \
        const int rr = tid >> 2, kq = tid & 3;                                  \
        As[st_][kq*4+0][rr]    = ar0.x; As[st_][kq*4+1][rr]    = ar0.y;         \
        As[st_][kq*4+2][rr]    = ar0.z; As[st_][kq*4+3][rr]    = ar0.w;         \
        As[st_][kq*4+0][rr+64] = ar1.x; As[st_][kq*4+1][rr+64] = ar1.y;         \
        As[st_][kq*4+2][rr+64] = ar1.z; As[st_][kq*4+3][rr+64] = ar1.w;         \
    } } while (0)

#define STORE_B(st_) do {                                                       \
    if (TN == 8) {                                                              \
        const int nr = tid >> 1, kq = tid & 1;                                  \
        Bs[st_][kq*8+0][nr] = br0.x; Bs[st_][kq*8+1][nr] = br0.y;               \
        Bs[st_][kq*8+2][nr] = br0.z; Bs[st_][kq*8+3][nr] = br0.w;               \
        Bs[st_][kq*8+4][nr] = br1.x; Bs[st_][kq*8+5][nr] = br1.y;               \
        Bs[st_][kq*8+6][nr] = br1.z; Bs[st_][kq*8+7][nr] = br1.w;               \
    } else {                                                                    \
        const int nr = tid >> 2, kq = tid & 3;                                  \
        Bs[st_][kq*4+0][nr] = br0.x; Bs[st_][kq*4+1][nr] = br0.y;               \
        Bs[st_][kq*4+2][nr] = br0.z; Bs[st_][kq*4+3][nr] = br0.w;               \
    } } while (0)

#define COMPUTE(st_) do {                                                       \
    _Pragma("unroll")                                                           \
    for (int kk = 0; kk < BKT; kk++) {                                          \
        const float* arow = &As[st_][kk][tm * 8];                               \
        ulonglong2 a01 = *(const ulonglong2*)(arow);                            \
        ulonglong2 a23 = *(const ulonglong2*)(arow + 4);                        \
        unsigned long long apk[4] = {a01.x, a01.y, a23.x, a23.y};               \
        float bv[TN];                                                           \
        *(float4*)&bv[0] = *(const float4*)&Bs[st_][kk][tn * TN];               \
        if (TN == 8)                                                            \
            *(float4*)&bv[4] = *(const float4*)&Bs[st_][kk][tn * TN + 4];       \
        _Pragma("unroll")                                                       \
        for (int j = 0; j < TN; j++) {                                          \
            unsigned long long bd = dup2(bv[j]);                                \
            _Pragma("unroll")                                                   \
            for (int p = 0; p < 4; p++) fma2(acc[j][p], apk[p], bd);            \
        }                                                                       \
    } } while (0)

    int k0 = kBase;
    LOAD_A(k0); LOAD_B(k0);
    STORE_A(0); STORE_B(0);
    __syncthreads();
    int st = 0;
    for (int t = 0; t < nT; t++) {
        const bool more = (t + 1 < nT);
        if (more) { LOAD_A(k0 + BKT); LOAD_B(k0 + BKT); }
        COMPUTE(st);
        if (more) {
            STORE_A(st ^ 1); STORE_B(st ^ 1);
            __syncthreads();
            st ^= 1; k0 += BKT;
        }
    }

#undef LOAD_A
#undef LOAD_B
#undef STORE_A
#undef STORE_B
#undef COMPUTE

    #pragma unroll
    for (int j = 0; j < TN; j++) {
        const int n = n0 + tn * TN + j;
        if (n >= N) continue;
        #pragma unroll
        for (int p = 0; p < 4; p++) {
            const int m = m0 + tm * 8 + 2 * p;
            float2 v = *reinterpret_cast<float2*>(&acc[j][p]);
            if (MODE == 0) {
                float* dst = C + (size_t)blockIdx.z * M * N + (size_t)m * N + n;
                dst[0] = v.x; dst[N] = v.y;
            } else if (MODE == 2) {
                const float bx = bias[n];
                float a0 = v.x + bx, a1 = v.y + bx;
                a0 = (a0 > 20.f) ? a0 : log1pf(expf(a0));
                a1 = (a1 > 20.f) ? a1 : log1pf(expf(a1));
                *reinterpret_cast<float2*>(C + (size_t)n * M + m) = make_float2(a0, a1);
            }
        }
    }
}

// split-K reduce + transpose: part[z][m][96] -> outT[96][2048]
__global__ void __launch_bounds__(256) reduceT_k(
    const float* __restrict__ part, float* __restrict__ outT)
{
    __shared__ float T[32][33];
    const int m0 = blockIdx.x * 32;
    const int n0 = blockIdx.y * 32;
    const int tx = threadIdx.x & 31, ty = threadIdx.x >> 5;   // ty 0..7
    #pragma unroll
    for (int k = 0; k < 4; k++) {
        const int m = m0 + ty + k * 8;
        float s = 0.f;
        #pragma unroll
        for (int z = 0; z < SPLITK; z++)
            s += part[(size_t)z * NTOK * XDBL_N + (size_t)m * XDBL_N + n0 + tx];
        T[ty + k * 8][tx] = s;
    }
    __syncthreads();
    #pragma unroll
    for (int k = 0; k < 4; k++)
        outT[(size_t)(n0 + ty + k * 8) * NTOK + m0 + tx] = T[tx][ty + k * 8];
}

__global__ void __launch_bounds__(256) conv_kernel(
    const float* __restrict__ xt, const float* __restrict__ cw,
    const float* __restrict__ cb, float* __restrict__ xct)
{
    const int row = blockIdx.x;
    const int d = row >> 1, b = row & 1;
    const size_t base = (size_t)d * NTOK + b * 1024;

    __shared__ float s[1024 + 3];
    const int tid = threadIdx.x;
    const float4 v = reinterpret_cast<const float4*>(xt + base)[tid];
    s[3 + tid*4 + 0] = v.x; s[3 + tid*4 + 1] = v.y;
    s[3 + tid*4 + 2] = v.z; s[3 + tid*4 + 3] = v.w;
    if (tid == 0) { s[0] = 0.f; s[1] = 0.f; s[2] = 0.f; }
    __syncthreads();

    const float w0 = cw[d*4+0], w1 = cw[d*4+1], w2 = cw[d*4+2], w3 = cw[d*4+3];
    const float bs = cb[d];
    float4 o;
    #pragma unroll
    for (int i = 0; i < 4; i++) {
        const int l = tid * 4 + i;
        float r = bs + w0*s[l] + w1*s[l+1] + w2*s[l+2] + w3*s[l+3];
        r = r / (1.f + __expf(-r));
        ((float*)&o)[i] = r;
    }
    reinterpret_cast<float4*>(xct + base)[tid] = o;
}

// scan with float4-vectorized loads from transposed xdblT
__global__ void __launch_bounds__(256) scan_kernel(
    const float* __restrict__ xdblT, const float* __restrict__ dtt,
    const float* __restrict__ xct,  const float* __restrict__ zt,
    const float* __restrict__ A_log, const float* __restrict__ Dp,
    float* __restrict__ yt)
{
    const int gt = blockIdx.x * blockDim.x + threadIdx.x;
    const int g = gt >> 4, s = gt & 15;
    const int b = g >> 11, d = g & 2047;

    const float Ac = -expf(A_log[d * DSTATE + s]);
    const float Dd = Dp[d];
    const size_t base = (size_t)d * NTOK + b * 1024;
    const float4* __restrict__ dtp = reinterpret_cast<const float4*>(dtt + base);
    const float4* __restrict__ xcp = reinterpret_cast<const float4*>(xct + base);
    const float4* __restrict__ zp  = reinterpret_cast<const float4*>(zt  + base);
    const float4* __restrict__ bsp = reinterpret_cast<const float4*>(
        xdblT + (size_t)(DTRANK + s) * NTOK + b * 1024);
    const float4* __restrict__ csp = reinterpret_cast<const float4*>(
        xdblT + (size_t)(DTRANK + DSTATE + s) * NTOK + b * 1024);
    float* __restrict__ yp = yt + (size_t)b * 1024 * DINNER + d;

    float h = 0.f;
    for (int q = 0; q < 256; q++) {
        const float4 d4 = dtp[q];
        const float4 x4 = xcp[q];
        const float4 z4 = zp[q];
        const float4 b4 = bsp[q];
        const float4 c4 = csp[q];
        #pragma unroll
        for (int i = 0; i < 4; i++) {
            const float dt  = (&d4.x)[i];
            const float xc  = (&x4.x)[i];
            const float bsv = (&b4.x)[i];
            const float csv = (&c4.x)[i];
            const float da = __expf(dt * Ac);
            h = fmaf(da, h, dt * bsv * xc);
            float p = h * csv;
            p += __shfl_xor_sync(0xffffffffu, p, 8, 16);
            p += __shfl_xor_sync(0xffffffffu, p, 4, 16);
            p += __shfl_xor_sync(0xffffffffu, p, 2, 16);
            p += __shfl_xor_sync(0xffffffffu, p, 1, 16);
            if (s == 0) {
                const float zv = (&z4.x)[i];
                const float gate = zv / (1.f + __expf(-zv));
                yp[(size_t)(q * 4 + i) * DINNER] = (p + xc * Dd) * gate;
            }
        }
    }
}

// ---------------------------------------------------------------------------
// host
// ---------------------------------------------------------------------------
extern "C" void kernel_launch(void* const* d_in, const int* in_sizes, int n_in,
                              void* d_out, int out_size)
{
    const float* x        = (const float*)d_in[0];
    const float* ln_w     = (const float*)d_in[1];
    const float* ln_b     = (const float*)d_in[2];
    const float* in_w     = (const float*)d_in[3];
    const float* conv_w   = (const float*)d_in[4];
    const float* conv_b   = (const float*)d_in[5];
    const float* xproj_w  = (const float*)d_in[6];
    const float* dtproj_w = (const float*)d_in[7];
    const float* dtproj_b = (const float*)d_in[8];
    const float* A_log    = (const float*)d_in[9];
    const float* Dp       = (const float*)d_in[10];
    const float* out_w    = (const float*)d_in[11];
    float* out = (float*)d_out;

    float *xt, *zt, *xct, *dtt, *yt, *xdblT, *xdblp, *opart;
    cudaGetSymbolAddress((void**)&xt,    g_xt);
    cudaGetSymbolAddress((void**)&zt,    g_zt);
    cudaGetSymbolAddress((void**)&xct,   g_xct);
    cudaGetSymbolAddress((void**)&dtt,   g_dtt);
    cudaGetSymbolAddress((void**)&yt,    g_yt);
    cudaGetSymbolAddress((void**)&xdblT, g_xdblT);
    cudaGetSymbolAddress((void**)&xdblp, g_xdbl_part);
    cudaGetSymbolAddress((void**)&opart, g_opart);

    __nv_bfloat16 *h_hi, *h_lo, *iw_hi, *iw_lo, *yt_hi, *yt_lo, *ow_hi, *ow_lo;
    cudaGetSymbolAddress((void**)&h_hi,  g_h_hi);
    cudaGetSymbolAddress((void**)&h_lo,  g_h_lo);
    cudaGetSymbolAddress((void**)&iw_hi, g_iw_hi);
    cudaGetSymbolAddress((void**)&iw_lo, g_iw_lo);
    cudaGetSymbolAddress((void**)&yt_hi, g_yt_hi);
    cudaGetSymbolAddress((void**)&yt_lo, g_yt_lo);
    cudaGetSymbolAddress((void**)&ow_hi, g_ow_hi);
    cudaGetSymbolAddress((void**)&ow_lo, g_ow_lo);

    cudaFuncSetAttribute(mm_gemm<0>, cudaFuncAttributeMaxDynamicSharedMemorySize,
                         MM_SMEM);
    cudaFuncSetAttribute(mm_gemm<1>, cudaFuncAttributeMaxDynamicSharedMemorySize,
                         MM_SMEM);

    // 1-2. independent weight splits first (puts mm0 in profile slot 4)
    cvt_split<<<(DMODEL * DINNER / 4) / 256, 256>>>(out_w, ow_hi, ow_lo,
                                                    DMODEL * DINNER / 4);
    cvt_split<<<(2 * DINNER * DMODEL / 4) / 256, 256>>>(in_w, iw_hi, iw_lo,
                                                        2 * DINNER * DMODEL / 4);
    // 3. layernorm -> bf16 hi/lo
    ln_kernel<<<NTOK, 256>>>(x, ln_w, ln_b, h_hi, h_lo);

    // 4. in_proj: M=2048, N=4096, K=1024 -> xt/zt channel-major
    mm_gemm<0><<<dim3(4096 / 128, NTOK / 128, 1), 256, MM_SMEM>>>(
        h_hi, h_lo, DMODEL, iw_hi, iw_lo, DMODEL, DMODEL / KC, xt, zt);

    // 5. depthwise conv + silu
    conv_kernel<<<DINNER * 2, 256>>>(xt, conv_w, conv_b, xct);

    // 6. x_proj (fp32 split-K) -> transpose-reduce to xdblT
    gemm_k<0, true, 4><<<dim3(2, NTOK / BM, SPLITK), 256>>>(
        xct, NTOK, xproj_w, xdblp, nullptr, nullptr, nullptr,
        NTOK, XDBL_N, DINNER, DINNER / SPLITK);
    reduceT_k<<<dim3(NTOK / 32, XDBL_N / 32), 256>>>(xdblp, xdblT);

    // 7. dt = softplus(xdblT[0:64]^T @ dtproj_w^T + b) -> dtt channel-major
    gemm_k<2, true, 8><<<dim3(DINNER / 128, NTOK / BM, 1), 256>>>(
        xdblT, NTOK, dtproj_w, dtt, nullptr, dtproj_b, nullptr,
        NTOK, DINNER, DTRANK, DTRANK);

    // 8. selective scan (vectorized) -> yt fp32 token-major
    scan_kernel<<<(2 * DINNER * DSTATE) / 256, 256>>>(
        xdblT, dtt, xct, zt, A_log, Dp, yt);

    // 9. split yt
    cvt_split<<<(NTOK * DINNER / 4) / 256, 256>>>(yt, yt_hi, yt_lo,
                                                  NTOK * DINNER / 4);

    // 10. out_proj split-K=2 partials
    mm_gemm<1><<<dim3(DMODEL / 128, NTOK / 128, 2), 256, MM_SMEM>>>(
        yt_hi, yt_lo, DINNER, ow_hi, ow_lo, DINNER, (DINNER / KC) / 2,
        opart, nullptr);

    // 11. reduce partials + residual
    add_out<<<(NTOK * DMODEL / 4) / 256, 256>>>(opart, x, out);
}

// round 11
// speedup vs baseline: 1.3935x; 1.3935x over previous
#include <cuda_runtime.h>
#include <cuda_bf16.h>
#include <cstdint>

// ---------------------------------------------------------------------------
// MambaBlock on GB300 (plain sm_103 -> mma.sync path).  R8 baseline (788us)
// + single change: scan vectorizes the broadcast streams (dt/xc/z) as float4,
// B/C stay token-major coalesced.
// ---------------------------------------------------------------------------

#define NTOK    2048
#define DMODEL  1024
#define DINNER  2048
#define DSTATE  16
#define DTRANK  64
#define XDBL_N  96
#define SPLITK  8

__device__ float g_h   [NTOK * DMODEL];
__device__ float g_xt  [DINNER * NTOK];
__device__ float g_zt  [DINNER * NTOK];
__device__ float g_xct [DINNER * NTOK];
__device__ float g_dtt [DINNER * NTOK];
__device__ float g_yt  [NTOK * DINNER];        // token-major
__device__ float g_xdbl[NTOK * XDBL_N];
__device__ float g_xdbl_part[SPLITK * NTOK * XDBL_N];

// pre-split bf16 hi/lo buffers
__device__ __nv_bfloat16 g_h_hi [NTOK * DMODEL];
__device__ __nv_bfloat16 g_h_lo [NTOK * DMODEL];
__device__ __nv_bfloat16 g_iw_hi[2 * DINNER * DMODEL];
__device__ __nv_bfloat16 g_iw_lo[2 * DINNER * DMODEL];
__device__ __nv_bfloat16 g_yt_hi[NTOK * DINNER];
__device__ __nv_bfloat16 g_yt_lo[NTOK * DINNER];
__device__ __nv_bfloat16 g_ow_hi[DMODEL * DINNER];
__device__ __nv_bfloat16 g_ow_lo[DMODEL * DINNER];

// =========================== helpers =======================================
__device__ __forceinline__ uint32_t smem_u32(const void* p) {
    uint32_t a;
    asm("{ .reg .u64 t; cvta.to.shared.u64 t, %1; cvt.u32.u64 %0, t; }"
        : "=r"(a) : "l"(p));
    return a;
}

__device__ __forceinline__ void ldm_x4(uint32_t* r, uint32_t addr) {
    asm volatile("ldmatrix.sync.aligned.m8n8.x4.shared.b16 {%0,%1,%2,%3}, [%4];"
        : "=r"(r[0]), "=r"(r[1]), "=r"(r[2]), "=r"(r[3]) : "r"(addr));
}

__device__ __forceinline__ void mma_bf16(float* c, const uint32_t* a,
                                         const uint32_t* b) {
    asm volatile(
        "mma.sync.aligned.m16n8k16.row.col.f32.bf16.bf16.f32 "
        "{%0,%1,%2,%3}, {%4,%5,%6,%7}, {%8,%9}, {%0,%1,%2,%3};"
        : "+f"(c[0]), "+f"(c[1]), "+f"(c[2]), "+f"(c[3])
        : "r"(a[0]), "r"(a[1]), "r"(a[2]), "r"(a[3]), "r"(b[0]), "r"(b[1]));
}

#define CP16(dst, src) \
    asm volatile("cp.async.cg.shared.global [%0], [%1], 16;" \
                 :: "r"(dst), "l"(src))
#define CP_COMMIT() asm volatile("cp.async.commit_group;" ::: "memory")

// fp32 -> bf16 hi/lo split (elementwise)
__global__ void __launch_bounds__(256) cvt_split(
    const float* __restrict__ src, __nv_bfloat16* __restrict__ hi,
    __nv_bfloat16* __restrict__ lo, int n4)
{
    const int i = blockIdx.x * 256 + threadIdx.x;
    if (i >= n4) return;
    const float4 v = reinterpret_cast<const float4*>(src)[i];
    __nv_bfloat162 h0 = __floats2bfloat162_rn(v.x, v.y);
    __nv_bfloat162 h1 = __floats2bfloat162_rn(v.z, v.w);
    __nv_bfloat162 l0 = __floats2bfloat162_rn(v.x - __bfloat162float(h0.x),
                                              v.y - __bfloat162float(h0.y));
    __nv_bfloat162 l1 = __floats2bfloat162_rn(v.z - __bfloat162float(h1.x),
                                              v.w - __bfloat162float(h1.y));
    reinterpret_cast<__nv_bfloat162*>(hi)[2*i]   = h0;
    reinterpret_cast<__nv_bfloat162*>(hi)[2*i+1] = h1;
    reinterpret_cast<__nv_bfloat162*>(lo)[2*i]   = l0;
    reinterpret_cast<__nv_bfloat162*>(lo)[2*i+1] = l1;
}

// ---------------------------------------------------------------------------
// bf16-split tensor GEMM (R8 config): CTA 128x128, 256 threads, 8 warps =
// 2(m) x 4(n), warp 64x32, Kc=32/stage, double-buffered cp.async.
// TMODE 0: channel-major store via smem transpose; n<2048 -> out0 else out1.
// TMODE 1: out0[m*1024+n] = D + resid[m*1024+n].
// Stage (bytes): Ahi[128][40]b16 @0, Alo @10240, Bhi @20480, Blo @30720.
// ---------------------------------------------------------------------------
#define KC 32
#define STG    40960
#define R_A_LO 10240
#define R_B_HI 20480
#define R_B_LO 30720
#define MM_SMEM 81920

template<int TMODE>
__global__ void __launch_bounds__(256, 2) mm_gemm(
    const __nv_bfloat16* __restrict__ Ahi, const __nv_bfloat16* __restrict__ Alo,
    int lda,
    const __nv_bfloat16* __restrict__ Bhi, const __nv_bfloat16* __restrict__ Blo,
    int ldb, int nchunk,
    float* __restrict__ out0, float* __restrict__ out1,
    const float* __restrict__ resid)
{
    extern __shared__ char smem_dyn[];
    const uint32_t sbase = smem_u32(smem_dyn);
    const int tid  = threadIdx.x;
    const int lane = tid & 31;
    const int w    = tid >> 5;
    const int wm   = w >> 2;
    const int wn   = w & 3;
    const int n0   = blockIdx.x * 128;
    const int m0   = blockIdx.y * 128;

    const int lrow  = tid >> 1;          // 0..127
    const int lhalf = (tid & 1) * 16;    // elements

    const int a_row  = wm * 64 + (lane & 15);
    const int a_coff = ((lane & 16) ? 16 : 0);
    const int b_row  = wn * 32 + ((lane >> 4) & 1) * 8 + (lane & 7);
    const int b_coff = ((lane & 8) ? 16 : 0);

    float acc[4][4][4];
    #pragma unroll
    for (int i = 0; i < 4; i++)
        #pragma unroll
        for (int j = 0; j < 4; j++)
            #pragma unroll
            for (int p = 0; p < 4; p++) acc[i][j][p] = 0.f;

#define ISSUE(c_, buf_) do {                                                    \
    const int kc0 = (c_) * KC;                                                  \
    const uint32_t sd = sbase + (buf_) * STG + lrow * 80 + lhalf * 2;           \
    const __nv_bfloat16* a0 = Ahi + (size_t)(m0 + lrow) * lda + kc0 + lhalf;    \
    const __nv_bfloat16* a1 = Alo + (size_t)(m0 + lrow) * lda + kc0 + lhalf;    \
    const __nv_bfloat16* b0 = Bhi + (size_t)(n0 + lrow) * ldb + kc0 + lhalf;    \
    const __nv_bfloat16* b1 = Blo + (size_t)(n0 + lrow) * ldb + kc0 + lhalf;    \
    CP16(sd,               a0);  CP16(sd + 16,          a0 + 8);                \
    CP16(sd + R_A_LO,      a1);  CP16(sd + R_A_LO + 16, a1 + 8);                \
    CP16(sd + R_B_HI,      b0);  CP16(sd + R_B_HI + 16, b0 + 8);                \
    CP16(sd + R_B_LO,      b1);  CP16(sd + R_B_LO + 16, b1 + 8);                \
    CP_COMMIT();                                                                \
    } while (0)

#define COMPUTE(buf_) do {                                                      \
    const uint32_t sa = sbase + (buf_) * STG;                                   \
    _Pragma("unroll")                                                           \
    for (int s = 0; s < 2; s++) {                                               \
        uint32_t Ah[4][4], Al[4][4], Bh[2][4], Bl[2][4];                        \
        _Pragma("unroll")                                                       \
        for (int mf = 0; mf < 4; mf++) {                                        \
            const uint32_t ar = sa + (a_row + mf * 16) * 80 + a_coff + s * 32;  \
            ldm_x4(Ah[mf], ar);                                                 \
            ldm_x4(Al[mf], ar + R_A_LO);                                        \
        }                                                                       \
        _Pragma("unroll")                                                       \
        for (int np = 0; np < 2; np++) {                                        \
            const uint32_t br = sa + R_B_HI + (b_row + np * 16) * 80            \
                                + b_coff + s * 32;                              \
            ldm_x4(Bh[np], br);                                                 \
            ldm_x4(Bl[np], br + (R_B_LO - R_B_HI));                             \
        }                                                                       \
        _Pragma("unroll")                                                       \
        for (int mf = 0; mf < 4; mf++)                                          \
            _Pragma("unroll")                                                   \
            for (int nf = 0; nf < 4; nf++) {                                    \
                const uint32_t* bh = &Bh[nf >> 1][(nf & 1) * 2];                \
                const uint32_t* bl = &Bl[nf >> 1][(nf & 1) * 2];                \
                mma_bf16(acc[mf][nf], Ah[mf], bh);                              \
                mma_bf16(acc[mf][nf], Ah[mf], bl);                              \
                mma_bf16(acc[mf][nf], Al[mf], bh);                              \
            }                                                                   \
    } } while (0)

    ISSUE(0, 0);
    for (int c = 0; c < nchunk; c++) {
        const int buf = c & 1;
        if (c + 1 < nchunk) {
            ISSUE(c + 1, buf ^ 1);
            asm volatile("cp.async.wait_group 1;" ::: "memory");
        } else {
            asm volatile("cp.async.wait_group 0;" ::: "memory");
        }
        __syncthreads();
        COMPUTE(buf);
        __syncthreads();
    }

#undef ISSUE
#undef COMPUTE

    const int rg = lane >> 2;
    const int cp = (lane & 3) * 2;

    if (TMODE == 0) {
        float* T = reinterpret_cast<float*>(smem_dyn);
        #pragma unroll
        for (int mf = 0; mf < 4; mf++)
            #pragma unroll
            for (int nf = 0; nf < 4; nf++) {
                const int m = wm * 64 + mf * 16 + rg;
                const int n = wn * 32 + nf * 8 + cp;
                T[(n    ) * 132 + m    ] = acc[mf][nf][0];
                T[(n + 1) * 132 + m    ] = acc[mf][nf][1];
                T[(n    ) * 132 + m + 8] = acc[mf][nf][2];
                T[(n + 1) * 132 + m + 8] = acc[mf][nf][3];
            }
        __syncthreads();
        float* ob; int nc0;
        if (n0 < 2048) { ob = out0; nc0 = n0; }
        else           { ob = out1; nc0 = n0 - 2048; }
        const int n  = tid >> 1;
        const int mh = (tid & 1) * 64;
        const float4* src = reinterpret_cast<const float4*>(&T[n * 132 + mh]);
        float4* dst = reinterpret_cast<float4*>(
            ob + (size_t)(nc0 + n) * NTOK + m0 + mh);
        #pragma unroll
        for (int j = 0; j < 16; j++) dst[j] = src[j];
    } else {
        #pragma unroll
        for (int mf = 0; mf < 4; mf++)
            #pragma unroll
            for (int nf = 0; nf < 4; nf++) {
                const int m = m0 + wm * 64 + mf * 16 + rg;
                const int n = n0 + wn * 32 + nf * 8 + cp;
                {
                    float2 rv = *reinterpret_cast<const float2*>(
                        resid + (size_t)m * DMODEL + n);
                    *reinterpret_cast<float2*>(out0 + (size_t)m * DMODEL + n) =
                        make_float2(acc[mf][nf][0] + rv.x, acc[mf][nf][1] + rv.y);
                }
                {
                    float2 rv = *reinterpret_cast<const float2*>(
                        resid + (size_t)(m + 8) * DMODEL + n);
                    *reinterpret_cast<float2*>(out0 + (size_t)(m + 8) * DMODEL + n) =
                        make_float2(acc[mf][nf][2] + rv.x, acc[mf][nf][3] + rv.y);
                }
            }
    }
}

// ============================ fp32 kernels =================================
__device__ __forceinline__ unsigned long long dup2(float x) {
    unsigned long long r;
    asm("mov.b64 %0, {%1, %1};" : "=l"(r) : "f"(x));
    return r;
}
__device__ __forceinline__ void fma2(unsigned long long& d,
                                     unsigned long long a,
                                     unsigned long long b) {
    asm("fma.rn.f32x2 %0, %1, %2, %0;" : "+l"(d) : "l"(a), "l"(b));
}

// LayerNorm -> bf16 hi/lo
__global__ void __launch_bounds__(256) ln_kernel(
    const float* __restrict__ x, const float* __restrict__ w,
    const float* __restrict__ b,
    __nv_bfloat16* __restrict__ hi, __nv_bfloat16* __restrict__ lo)
{
    const int t = blockIdx.x;
    const float4 v = reinterpret_cast<const float4*>(x + (size_t)t * DMODEL)[threadIdx.x];
    float s  = v.x + v.y + v.z + v.w;
    float sq = v.x*v.x + v.y*v.y + v.z*v.z + v.w*v.w;

    __shared__ float sa[8], sb2[8];
    int lane = threadIdx.x & 31, wrp = threadIdx.x >> 5;
    #pragma unroll
    for (int o = 16; o; o >>= 1) {
        s  += __shfl_down_sync(0xffffffffu, s,  o);
        sq += __shfl_down_sync(0xffffffffu, sq, o);
    }
    if (lane == 0) { sa[wrp] = s; sb2[wrp] = sq; }
    __syncthreads();
    if (wrp == 0) {
        s  = (lane < 8) ? sa[lane] : 0.f;
        sq = (lane < 8) ? sb2[lane] : 0.f;
        #pragma unroll
        for (int o = 4; o; o >>= 1) {
            s  += __shfl_down_sync(0xffffffffu, s,  o);
            sq += __shfl_down_sync(0xffffffffu, sq, o);
        }
        if (lane == 0) { sa[0] = s; sb2[0] = sq; }
    }
    __syncthreads();
    const float mu  = sa[0] * (1.f / DMODEL);
    const float var = sb2[0] * (1.f / DMODEL) - mu * mu;
    const float inv = rsqrtf(var + 1e-5f);

    const float4 wv = reinterpret_cast<const float4*>(w)[threadIdx.x];
    const float4 bv = reinterpret_cast<const float4*>(b)[threadIdx.x];
    float4 o4;
    o4.x = (v.x - mu) * inv * wv.x + bv.x;
    o4.y = (v.y - mu) * inv * wv.y + bv.y;
    o4.z = (v.z - mu) * inv * wv.z + bv.z;
    o4.w = (v.w - mu) * inv * wv.w + bv.w;

    __nv_bfloat162 h0 = __floats2bfloat162_rn(o4.x, o4.y);
    __nv_bfloat162 h1 = __floats2bfloat162_rn(o4.z, o4.w);
    __nv_bfloat162 l0 = __floats2bfloat162_rn(o4.x - __bfloat162float(h0.x),
                                              o4.y - __bfloat162float(h0.y));
    __nv_bfloat162 l1 = __floats2bfloat162_rn(o4.z - __bfloat162float(h1.x),
                                              o4.w - __bfloat162float(h1.y));
    const size_t base2 = ((size_t)t * DMODEL) / 2 + threadIdx.x * 2;
    reinterpret_cast<__nv_bfloat162*>(hi)[base2]     = h0;
    reinterpret_cast<__nv_bfloat162*>(hi)[base2 + 1] = h1;
    reinterpret_cast<__nv_bfloat162*>(lo)[base2]     = l0;
    reinterpret_cast<__nv_bfloat162*>(lo)[base2 + 1] = l1;
}

#define BM  128
#define BKT 16
#define APAD 4

template<int MODE, bool ACOL, int TN>
__global__ void __launch_bounds__(256) gemm_k(
    const float* __restrict__ A, int lda, const float* __restrict__ B,
    float* __restrict__ C, float* __restrict__ C2,
    const float* __restrict__ bias, const float* __restrict__ resid,
    int M, int N, int K, int kSplitLen)
{
    constexpr int BN = TN * 16;
    __shared__ __align__(16) float As[2][BKT][BM + APAD];
    __shared__ __align__(16) float Bs[2][BKT][BN];

    const int tid = threadIdx.x;
    const int n0 = blockIdx.x * BN;
    const int m0 = blockIdx.y * BM;
    const int kBase = blockIdx.z * kSplitLen;
    const int nT = kSplitLen / BKT;
    const int tm = tid >> 4, tn = tid & 15;

    unsigned long long acc[TN][4];
    #pragma unroll
    for (int j = 0; j < TN; j++)
        #pragma unroll
        for (int p = 0; p < 4; p++) acc[j][p] = 0ull;

    float4 ar0, ar1, br0, br1;

#define LOAD_A(k0_) do {                                                        \
    if (ACOL) {                                                                 \
        const int m4 = tid & 31, kr = tid >> 5;                                 \
        ar0 = *(const float4*)(A + (size_t)((k0_) + kr)     * lda + m0 + m4*4); \
        ar1 = *(const float4*)(A + (size_t)((k0_) + kr + 8) * lda + m0 + m4*4); \
    } else {                                                                    \
        const int rr = tid >> 2, kq = tid & 3;                                  \
        ar0 = *(const float4*)(A + (size_t)(m0 + rr)      * lda + (k0_) + kq*4);\
        ar1 = *(const float4*)(A + (size_t)(m0 + rr + 64) * lda + (k0_) + kq*4);\
    } } while (0)

#define LOAD_B(k0_) do {                                                        \
    if (TN == 8) {                                                              \
        const int nr = tid >> 1, kq = tid & 1;                                  \
        if (n0 + nr < N) {                                                      \
            const float* bp = B + (size_t)(n0 + nr) * K + (k0_) + kq * 8;       \
            br0 = *(const float4*)(bp);                                         \
            br1 = *(const float4*)(bp + 4);                                     \
        } else { br0 = make_float4(0,0,0,0); br1 = br0; }                       \
    } else {                                                                    \
        const int nr = tid >> 2, kq = tid & 3;                                  \
        br0 = (n0 + nr < N)                                                     \
            ? *(const float4*)(B + (size_t)(n0 + nr) * K + (k0_) + kq*4)        \
            : make_float4(0,0,0,0);                                             \
    } } while (0)

#define STORE_A(st_) do {                                                       \
    if (ACOL) {                                                                 \
        const int m4 = tid & 31, kr = tid >> 5;                                 \
        *(float4*)&As[st_][kr  ][m4*4] = ar0;                                   \
        *(float4*)&As[st_][kr+8][m4*4] = ar1;                                   \
    } else {                                                                    \
        const int rr = tid >> 2, kq = tid & 3;                                  \
        As[st_][kq*4+0][rr]    = ar0.x; As[st_][kq*4+1][rr]    = ar0.y;         \
        As[st_][kq*4+2][rr]    = ar0.z; As[st_][kq*4+3][rr]    = ar0.w;         \
        As[st_][kq*4+0][rr+64] = ar1.x; As[st_][kq*4+1][rr+64] = ar1.y;         \
        As[st_][kq*4+2][rr+64] = ar1.z; As[st_][kq*4+3][rr+64] = ar1.w;         \
    } } while (0)

#define STORE_B(st_) do {                                                       \
    if (TN == 8) {                                                              \
        const int nr = tid >> 1, kq = tid & 1;                                  \
        Bs[st_][kq*8+0][nr] = br0.x; Bs[st_][kq*8+1][nr] = br0.y;               \
        Bs[st_][kq*8+2][nr] = br0.z; Bs[st_][kq*8+3][nr] = br0.w;               \
        Bs[st_][kq*8+4][nr] = br1.x; Bs[st_][kq*8+5][nr] = br1.y;               \
        Bs[st_][kq*8+6][nr] = br1.z; Bs[st_][kq*8+7][nr] = br1.w;               \
    } else {                                                                    \
        const int nr = tid >> 2, kq = tid & 3;                                  \
        Bs[st_][kq*4+0][nr] = br0.x; Bs[st_][kq*4+1][nr] = br0.y;               \
        Bs[st_][kq*4+2][nr] = br0.z; Bs[st_][kq*4+3][nr] = br0.w;               \
    } } while (0)

#define COMPUTE(st_) do {                                                       \
    _Pragma("unroll")                                                           \
    for (int kk = 0; kk < BKT; kk++) {                                          \
        const float* arow = &As[st_][kk][tm * 8];                               \
        ulonglong2 a01 = *(const ulonglong2*)(arow);                            \
        ulonglong2 a23 = *(const ulonglong2*)(arow + 4);                        \
        unsigned long long apk[4] = {a01.x, a01.y, a23.x, a23.y};               \
        float bv[TN];                                                           \
        *(float4*)&bv[0] = *(const float4*)&Bs[st_][kk][tn * TN];               \
        if (TN == 8)                                                            \
            *(float4*)&bv[4] = *(const float4*)&Bs[st_][kk][tn * TN + 4];       \
        _Pragma("unroll")                                                       \
        for (int j = 0; j < TN; j++) {                                          \
            unsigned long long bd = dup2(bv[j]);                                \
            _Pragma("unroll")                                                   \
            for (int p = 0; p < 4; p++) fma2(acc[j][p], apk[p], bd);            \
        }                                                                       \
    } } while (0)

    int k0 = kBase;
    LOAD_A(k0); LOAD_B(k0);
    STORE_A(0); STORE_B(0);
    __syncthreads();
    int st = 0;
    for (int t = 0; t < nT; t++) {
        const bool more = (t + 1 < nT);
        if (more) { LOAD_A(k0 + BKT); LOAD_B(k0 + BKT); }
        COMPUTE(st);
        if (more) {
            STORE_A(st ^ 1); STORE_B(st ^ 1);
            __syncthreads();
            st ^= 1; k0 += BKT;
        }
    }

#undef LOAD_A
#undef LOAD_B
#undef STORE_A
#undef STORE_B
#undef COMPUTE

    #pragma unroll
    for (int j = 0; j < TN; j++) {
        const int n = n0 + tn * TN + j;
        if (n >= N) continue;
        #pragma unroll
        for (int p = 0; p < 4; p++) {
            const int m = m0 + tm * 8 + 2 * p;
            float2 v = *reinterpret_cast<float2*>(&acc[j][p]);
            if (MODE == 0) {
                float* dst = C + (size_t)blockIdx.z * M * N + (size_t)m * N + n;
                dst[0] = v.x; dst[N] = v.y;
            } else if (MODE == 2) {
                const float bx = bias[n];
                float a0 = v.x + bx, a1 = v.y + bx;
                a0 = (a0 > 20.f) ? a0 : log1pf(expf(a0));
                a1 = (a1 > 20.f) ? a1 : log1pf(expf(a1));
                *reinterpret_cast<float2*>(C + (size_t)n * M + m) = make_float2(a0, a1);
            }
        }
    }
}

__global__ void __launch_bounds__(256) reduce_k(
    const float* __restrict__ part, float* __restrict__ out, int n)
{
    const int i = blockIdx.x * 256 + threadIdx.x;
    if (i < n) {
        float s = 0.f;
        #pragma unroll
        for (int z = 0; z < SPLITK; z++) s += part[(size_t)z * n + i];
        out[i] = s;
    }
}

__global__ void __launch_bounds__(256) conv_kernel(
    const float* __restrict__ xt, const float* __restrict__ cw,
    const float* __restrict__ cb, float* __restrict__ xct)
{
    const int row = blockIdx.x;
    const int d = row >> 1, b = row & 1;
    const size_t base = (size_t)d * NTOK + b * 1024;

    __shared__ float s[1024 + 3];
    const int tid = threadIdx.x;
    const float4 v = reinterpret_cast<const float4*>(xt + base)[tid];
    s[3 + tid*4 + 0] = v.x; s[3 + tid*4 + 1] = v.y;
    s[3 + tid*4 + 2] = v.z; s[3 + tid*4 + 3] = v.w;
    if (tid == 0) { s[0] = 0.f; s[1] = 0.f; s[2] = 0.f; }
    __syncthreads();

    const float w0 = cw[d*4+0], w1 = cw[d*4+1], w2 = cw[d*4+2], w3 = cw[d*4+3];
    const float bs = cb[d];
    float4 o;
    #pragma unroll
    for (int i = 0; i < 4; i++) {
        const int l = tid * 4 + i;
        float r = bs + w0*s[l] + w1*s[l+1] + w2*s[l+2] + w3*s[l+3];
        r = r / (1.f + __expf(-r));
        ((float*)&o)[i] = r;
    }
    reinterpret_cast<float4*>(xct + base)[tid] = o;
}

// scan: broadcast streams (dt/xc/z) via float4 every 4 steps; B/C token-major
// coalesced scalar loads (same as R8); yt fp32 token-major.
__global__ void __launch_bounds__(256) scan_kernel(
    const float* __restrict__ xdbl, const float* __restrict__ dtt,
    const float* __restrict__ xct,  const float* __restrict__ zt,
    const float* __restrict__ A_log, const float* __restrict__ Dp,
    float* __restrict__ yt)
{
    const int gt = blockIdx.x * blockDim.x + threadIdx.x;
    const int g = gt >> 4, s = gt & 15;
    const int b = g >> 11, d = g & 2047;

    const float Ac = -expf(A_log[d * DSTATE + s]);
    const float Dd = Dp[d];
    const size_t base = (size_t)d * NTOK + b * 1024;
    const float4* __restrict__ dtp = reinterpret_cast<const float4*>(dtt + base);
    const float4* __restrict__ xcp = reinterpret_cast<const float4*>(xct + base);
    const float4* __restrict__ zp  = reinterpret_cast<const float4*>(zt  + base);
    float* __restrict__ yp = yt + (size_t)b * 1024 * DINNER + d;
    const float* __restrict__ xd = xdbl + (size_t)(b * 1024) * XDBL_N;

    float h = 0.f;
    for (int q = 0; q < 256; q++) {
        const float4 d4 = dtp[q];
        const float4 x4 = xcp[q];
        const float4 z4 = zp[q];
        #pragma unroll
        for (int i = 0; i < 4; i++) {
            const int t = q * 4 + i;
            const float dt  = (&d4.x)[i];
            const float xc  = (&x4.x)[i];
            const float bsv = xd[t * XDBL_N + DTRANK + s];
            const float csv = xd[t * XDBL_N + DTRANK + DSTATE + s];
            const float da = __expf(dt * Ac);
            h = fmaf(da, h, dt * bsv * xc);
            float p = h * csv;
            p += __shfl_xor_sync(0xffffffffu, p, 8, 16);
            p += __shfl_xor_sync(0xffffffffu, p, 4, 16);
            p += __shfl_xor_sync(0xffffffffu, p, 2, 16);
            p += __shfl_xor_sync(0xffffffffu, p, 1, 16);
            if (s == 0) {
                const float zv = (&z4.x)[i];
                const float gate = zv / (1.f + __expf(-zv));
                yp[(size_t)t * DINNER] = (p + xc * Dd) * gate;
            }
        }
    }
}

// ---------------------------------------------------------------------------
// host
// ---------------------------------------------------------------------------
extern "C" void kernel_launch(void* const* d_in, const int* in_sizes, int n_in,
                              void* d_out, int out_size)
{
    const float* x        = (const float*)d_in[0];
    const float* ln_w     = (const float*)d_in[1];
    const float* ln_b     = (const float*)d_in[2];
    const float* in_w     = (const float*)d_in[3];
    const float* conv_w   = (const float*)d_in[4];
    const float* conv_b   = (const float*)d_in[5];
    const float* xproj_w  = (const float*)d_in[6];
    const float* dtproj_w = (const float*)d_in[7];
    const float* dtproj_b = (const float*)d_in[8];
    const float* A_log    = (const float*)d_in[9];
    const float* Dp       = (const float*)d_in[10];
    const float* out_w    = (const float*)d_in[11];
    float* out = (float*)d_out;

    float *xt, *zt, *xct, *dtt, *yt, *xdbl, *xdblp;
    cudaGetSymbolAddress((void**)&xt,    g_xt);
    cudaGetSymbolAddress((void**)&zt,    g_zt);
    cudaGetSymbolAddress((void**)&xct,   g_xct);
    cudaGetSymbolAddress((void**)&dtt,   g_dtt);
    cudaGetSymbolAddress((void**)&yt,    g_yt);
    cudaGetSymbolAddress((void**)&xdbl,  g_xdbl);
    cudaGetSymbolAddress((void**)&xdblp, g_xdbl_part);

    __nv_bfloat16 *h_hi, *h_lo, *iw_hi, *iw_lo, *yt_hi, *yt_lo, *ow_hi, *ow_lo;
    cudaGetSymbolAddress((void**)&h_hi,  g_h_hi);
    cudaGetSymbolAddress((void**)&h_lo,  g_h_lo);
    cudaGetSymbolAddress((void**)&iw_hi, g_iw_hi);
    cudaGetSymbolAddress((void**)&iw_lo, g_iw_lo);
    cudaGetSymbolAddress((void**)&yt_hi, g_yt_hi);
    cudaGetSymbolAddress((void**)&yt_lo, g_yt_lo);
    cudaGetSymbolAddress((void**)&ow_hi, g_ow_hi);
    cudaGetSymbolAddress((void**)&ow_lo, g_ow_lo);

    cudaFuncSetAttribute(mm_gemm<0>, cudaFuncAttributeMaxDynamicSharedMemorySize,
                         MM_SMEM);
    cudaFuncSetAttribute(mm_gemm<1>, cudaFuncAttributeMaxDynamicSharedMemorySize,
                         MM_SMEM);

    // 1-2. weight splits first (keeps mm0 in the profiled slot)
    cvt_split<<<(DMODEL * DINNER / 4) / 256, 256>>>(out_w, ow_hi, ow_lo,
                                                    DMODEL * DINNER / 4);
    cvt_split<<<(2 * DINNER * DMODEL / 4) / 256, 256>>>(in_w, iw_hi, iw_lo,
                                                        2 * DINNER * DMODEL / 4);
    // 3. layernorm -> bf16 hi/lo
    ln_kernel<<<NTOK, 256>>>(x, ln_w, ln_b, h_hi, h_lo);

    // 4. in_proj: M=2048, N=4096, K=1024 -> xt/zt channel-major
    mm_gemm<0><<<dim3(4096 / 128, NTOK / 128), 256, MM_SMEM>>>(
        h_hi, h_lo, DMODEL, iw_hi, iw_lo, DMODEL, DMODEL / KC, xt, zt, nullptr);

    // 5. depthwise conv + silu
    conv_kernel<<<DINNER * 2, 256>>>(xt, conv_w, conv_b, xct);

    // 6. x_proj (fp32 split-K)
    gemm_k<0, true, 4><<<dim3(2, NTOK / BM, SPLITK), 256>>>(
        xct, NTOK, xproj_w, xdblp, nullptr, nullptr, nullptr,
        NTOK, XDBL_N, DINNER, DINNER / SPLITK);
    reduce_k<<<(NTOK * XDBL_N + 255) / 256, 256>>>(xdblp, xdbl, NTOK * XDBL_N);

    // 7. dt = softplus(...) (fp32)
    gemm_k<2, false, 8><<<dim3(DINNER / 128, NTOK / BM, 1), 256>>>(
        xdbl, XDBL_N, dtproj_w, dtt, nullptr, dtproj_b, nullptr,
        NTOK, DINNER, DTRANK, DTRANK);

    // 8. selective scan -> yt fp32 token-major
    scan_kernel<<<(2 * DINNER * DSTATE) / 256, 256>>>(
        xdbl, dtt, xct, zt, A_log, Dp, yt);

    // 9. split yt
    cvt_split<<<(NTOK * DINNER / 4) / 256, 256>>>(yt, yt_hi, yt_lo,
                                                  NTOK * DINNER / 4);

    // 10. out_proj + residual (R8 form, no split-K)
    mm_gemm<1><<<dim3(DMODEL / 128, NTOK / 128), 256, MM_SMEM>>>(
        yt_hi, yt_lo, DINNER, ow_hi, ow_lo, DINNER, DINNER / KC, out, nullptr, x);
}

// round 13
// speedup vs baseline: 1.4188x; 1.0182x over previous
#include <cuda_runtime.h>
#include <cuda_bf16.h>
#include <cstdint>

// ---------------------------------------------------------------------------
// MambaBlock on GB300 (plain sm_103 -> mma.sync path).  R11 baseline (745us)
// + single change: out_proj split-K=2 (256 CTAs = full wave) with fused
// partial-reduce + residual epilogue kernel.
// ---------------------------------------------------------------------------

#define NTOK    2048
#define DMODEL  1024
#define DINNER  2048
#define DSTATE  16
#define DTRANK  64
#define XDBL_N  96
#define SPLITK  8

__device__ float g_xt  [DINNER * NTOK];
__device__ float g_zt  [DINNER * NTOK];
__device__ float g_xct [DINNER * NTOK];
__device__ float g_dtt [DINNER * NTOK];
__device__ float g_yt  [NTOK * DINNER];        // token-major
__device__ float g_xdbl[NTOK * XDBL_N];
__device__ float g_xdbl_part[SPLITK * NTOK * XDBL_N];
__device__ float g_opart[2 * NTOK * DMODEL];   // out_proj split-K partials

// pre-split bf16 hi/lo buffers
__device__ __nv_bfloat16 g_h_hi [NTOK * DMODEL];
__device__ __nv_bfloat16 g_h_lo [NTOK * DMODEL];
__device__ __nv_bfloat16 g_iw_hi[2 * DINNER * DMODEL];
__device__ __nv_bfloat16 g_iw_lo[2 * DINNER * DMODEL];
__device__ __nv_bfloat16 g_yt_hi[NTOK * DINNER];
__device__ __nv_bfloat16 g_yt_lo[NTOK * DINNER];
__device__ __nv_bfloat16 g_ow_hi[DMODEL * DINNER];
__device__ __nv_bfloat16 g_ow_lo[DMODEL * DINNER];

// =========================== helpers =======================================
__device__ __forceinline__ uint32_t smem_u32(const void* p) {
    uint32_t a;
    asm("{ .reg .u64 t; cvta.to.shared.u64 t, %1; cvt.u32.u64 %0, t; }"
        : "=r"(a) : "l"(p));
    return a;
}

__device__ __forceinline__ void ldm_x4(uint32_t* r, uint32_t addr) {
    asm volatile("ldmatrix.sync.aligned.m8n8.x4.shared.b16 {%0,%1,%2,%3}, [%4];"
        : "=r"(r[0]), "=r"(r[1]), "=r"(r[2]), "=r"(r[3]) : "r"(addr));
}

__device__ __forceinline__ void mma_bf16(float* c, const uint32_t* a,
                                         const uint32_t* b) {
    asm volatile(
        "mma.sync.aligned.m16n8k16.row.col.f32.bf16.bf16.f32 "
        "{%0,%1,%2,%3}, {%4,%5,%6,%7}, {%8,%9}, {%0,%1,%2,%3};"
        : "+f"(c[0]), "+f"(c[1]), "+f"(c[2]), "+f"(c[3])
        : "r"(a[0]), "r"(a[1]), "r"(a[2]), "r"(a[3]), "r"(b[0]), "r"(b[1]));
}

#define CP16(dst, src) \
    asm volatile("cp.async.cg.shared.global [%0], [%1], 16;" \
                 :: "r"(dst), "l"(src))
#define CP_COMMIT() asm volatile("cp.async.commit_group;" ::: "memory")

// fp32 -> bf16 hi/lo split (elementwise)
__global__ void __launch_bounds__(256) cvt_split(
    const float* __restrict__ src, __nv_bfloat16* __restrict__ hi,
    __nv_bfloat16* __restrict__ lo, int n4)
{
    const int i = blockIdx.x * 256 + threadIdx.x;
    if (i >= n4) return;
    const float4 v = reinterpret_cast<const float4*>(src)[i];
    __nv_bfloat162 h0 = __floats2bfloat162_rn(v.x, v.y);
    __nv_bfloat162 h1 = __floats2bfloat162_rn(v.z, v.w);
    __nv_bfloat162 l0 = __floats2bfloat162_rn(v.x - __bfloat162float(h0.x),
                                              v.y - __bfloat162float(h0.y));
    __nv_bfloat162 l1 = __floats2bfloat162_rn(v.z - __bfloat162float(h1.x),
                                              v.w - __bfloat162float(h1.y));
    reinterpret_cast<__nv_bfloat162*>(hi)[2*i]   = h0;
    reinterpret_cast<__nv_bfloat162*>(hi)[2*i+1] = h1;
    reinterpret_cast<__nv_bfloat162*>(lo)[2*i]   = l0;
    reinterpret_cast<__nv_bfloat162*>(lo)[2*i+1] = l1;
}

// ---------------------------------------------------------------------------
// bf16-split tensor GEMM (R8 config): CTA 128x128, 256 threads, 8 warps =
// 2(m) x 4(n), warp 64x32, Kc=32/stage, double-buffered cp.async.
// TMODE 0: channel-major store via smem transpose; n<2048 -> out0 else out1.
// TMODE 1: split-K partial: out0[z*NTOK*DMODEL + m*DMODEL + n] = D.
// Stage (bytes): Ahi[128][40]b16 @0, Alo @10240, Bhi @20480, Blo @30720.
// ---------------------------------------------------------------------------
#define KC 32
#define STG    40960
#define R_A_LO 10240
#define R_B_HI 20480
#define R_B_LO 30720
#define MM_SMEM 81920

template<int TMODE>
__global__ void __launch_bounds__(256, 2) mm_gemm(
    const __nv_bfloat16* __restrict__ Ahi, const __nv_bfloat16* __restrict__ Alo,
    int lda,
    const __nv_bfloat16* __restrict__ Bhi, const __nv_bfloat16* __restrict__ Blo,
    int ldb, int nchunk,
    float* __restrict__ out0, float* __restrict__ out1,
    const float* __restrict__ resid)
{
    extern __shared__ char smem_dyn[];
    const uint32_t sbase = smem_u32(smem_dyn);
    const int tid  = threadIdx.x;
    const int lane = tid & 31;
    const int w    = tid >> 5;
    const int wm   = w >> 2;
    const int wn   = w & 3;
    const int n0   = blockIdx.x * 128;
    const int m0   = blockIdx.y * 128;
    const int kbase = blockIdx.z * nchunk;

    const int lrow  = tid >> 1;          // 0..127
    const int lhalf = (tid & 1) * 16;    // elements

    const int a_row  = wm * 64 + (lane & 15);
    const int a_coff = ((lane & 16) ? 16 : 0);
    const int b_row  = wn * 32 + ((lane >> 4) & 1) * 8 + (lane & 7);
    const int b_coff = ((lane & 8) ? 16 : 0);

    float acc[4][4][4];
    #pragma unroll
    for (int i = 0; i < 4; i++)
        #pragma unroll
        for (int j = 0; j < 4; j++)
            #pragma unroll
            for (int p = 0; p < 4; p++) acc[i][j][p] = 0.f;

#define ISSUE(c_, buf_) do {                                                    \
    const int kc0 = (c_) * KC;                                                  \
    const uint32_t sd = sbase + (buf_) * STG + lrow * 80 + lhalf * 2;           \
    const __nv_bfloat16* a0 = Ahi + (size_t)(m0 + lrow) * lda + kc0 + lhalf;    \
    const __nv_bfloat16* a1 = Alo + (size_t)(m0 + lrow) * lda + kc0 + lhalf;    \
    const __nv_bfloat16* b0 = Bhi + (size_t)(n0 + lrow) * ldb + kc0 + lhalf;    \
    const __nv_bfloat16* b1 = Blo + (size_t)(n0 + lrow) * ldb + kc0 + lhalf;    \
    CP16(sd,               a0);  CP16(sd + 16,          a0 + 8);                \
    CP16(sd + R_A_LO,      a1);  CP16(sd + R_A_LO + 16, a1 + 8);                \
    CP16(sd + R_B_HI,      b0);  CP16(sd + R_B_HI + 16, b0 + 8);                \
    CP16(sd + R_B_LO,      b1);  CP16(sd + R_B_LO + 16, b1 + 8);                \
    CP_COMMIT();                                                                \
    } while (0)

#define COMPUTE(buf_) do {                                                      \
    const uint32_t sa = sbase + (buf_) * STG;                                   \
    _Pragma("unroll")                                                           \
    for (int s = 0; s < 2; s++) {                                               \
        uint32_t Ah[4][4], Al[4][4], Bh[2][4], Bl[2][4];                        \
        _Pragma("unroll")                                                       \
        for (int mf = 0; mf < 4; mf++) {                                        \
            const uint32_t ar = sa + (a_row + mf * 16) * 80 + a_coff + s * 32;  \
            ldm_x4(Ah[mf], ar);                                                 \
            ldm_x4(Al[mf], ar + R_A_LO);                                        \
        }                                                                       \
        _Pragma("unroll")                                                       \
        for (int np = 0; np < 2; np++) {                                        \
            const uint32_t br = sa + R_B_HI + (b_row + np * 16) * 80            \
                                + b_coff + s * 32;                              \
            ldm_x4(Bh[np], br);                                                 \
            ldm_x4(Bl[np], br + (R_B_LO - R_B_HI));                             \
        }                                                                       \
        _Pragma("unroll")                                                       \
        for (int mf = 0; mf < 4; mf++)                                          \
            _Pragma("unroll")                                                   \
            for (int nf = 0; nf < 4; nf++) {                                    \
                const uint32_t* bh = &Bh[nf >> 1][(nf & 1) * 2];                \
                const uint32_t* bl = &Bl[nf >> 1][(nf & 1) * 2];                \
                mma_bf16(acc[mf][nf], Ah[mf], bh);                              \
                mma_bf16(acc[mf][nf], Ah[mf], bl);                              \
                mma_bf16(acc[mf][nf], Al[mf], bh);                              \
            }                                                                   \
    } } while (0)

    ISSUE(kbase, 0);
    for (int c = 0; c < nchunk; c++) {
        const int buf = c & 1;
        if (c + 1 < nchunk) {
            ISSUE(kbase + c + 1, buf ^ 1);
            asm volatile("cp.async.wait_group 1;" ::: "memory");
        } else {
            asm volatile("cp.async.wait_group 0;" ::: "memory");
        }
        __syncthreads();
        COMPUTE(buf);
        __syncthreads();
    }

#undef ISSUE
#undef COMPUTE

    const int rg = lane >> 2;
    const int cp = (lane & 3) * 2;

    if (TMODE == 0) {
        float* T = reinterpret_cast<float*>(smem_dyn);
        #pragma unroll
        for (int mf = 0; mf < 4; mf++)
            #pragma unroll
            for (int nf = 0; nf < 4; nf++) {
                const int m = wm * 64 + mf * 16 + rg;
                const int n = wn * 32 + nf * 8 + cp;
                T[(n    ) * 132 + m    ] = acc[mf][nf][0];
                T[(n + 1) * 132 + m    ] = acc[mf][nf][1];
                T[(n    ) * 132 + m + 8] = acc[mf][nf][2];
                T[(n + 1) * 132 + m + 8] = acc[mf][nf][3];
            }
        __syncthreads();
        float* ob; int nc0;
        if (n0 < 2048) { ob = out0; nc0 = n0; }
        else           { ob = out1; nc0 = n0 - 2048; }
        const int n  = tid >> 1;
        const int mh = (tid & 1) * 64;
        const float4* src = reinterpret_cast<const float4*>(&T[n * 132 + mh]);
        float4* dst = reinterpret_cast<float4*>(
            ob + (size_t)(nc0 + n) * NTOK + m0 + mh);
        #pragma unroll
        for (int j = 0; j < 16; j++) dst[j] = src[j];
    } else {
        float* part = out0 + (size_t)blockIdx.z * NTOK * DMODEL;
        #pragma unroll
        for (int mf = 0; mf < 4; mf++)
            #pragma unroll
            for (int nf = 0; nf < 4; nf++) {
                const int m = m0 + wm * 64 + mf * 16 + rg;
                const int n = n0 + wn * 32 + nf * 8 + cp;
                *reinterpret_cast<float2*>(part + (size_t)m * DMODEL + n) =
                    make_float2(acc[mf][nf][0], acc[mf][nf][1]);
                *reinterpret_cast<float2*>(part + (size_t)(m + 8) * DMODEL + n) =
                    make_float2(acc[mf][nf][2], acc[mf][nf][3]);
            }
    }
}

// out = part0 + part1 + x   (split-K reduce + residual)
__global__ void __launch_bounds__(256) add_out(
    const float* __restrict__ part, const float* __restrict__ x,
    float* __restrict__ out)
{
    const int i = blockIdx.x * 256 + threadIdx.x;
    const float4 a = reinterpret_cast<const float4*>(part)[i];
    const float4 b = reinterpret_cast<const float4*>(part + NTOK * DMODEL)[i];
    const float4 c = reinterpret_cast<const float4*>(x)[i];
    float4 o;
    o.x = a.x + b.x + c.x; o.y = a.y + b.y + c.y;
    o.z = a.z + b.z + c.z; o.w = a.w + b.w + c.w;
    reinterpret_cast<float4*>(out)[i] = o;
}

// ============================ fp32 kernels =================================
__device__ __forceinline__ unsigned long long dup2(float x) {
    unsigned long long r;
    asm("mov.b64 %0, {%1, %1};" : "=l"(r) : "f"(x));
    return r;
}
__device__ __forceinline__ void fma2(unsigned long long& d,
                                     unsigned long long a,
                                     unsigned long long b) {
    asm("fma.rn.f32x2 %0, %1, %2, %0;" : "+l"(d) : "l"(a), "l"(b));
}

// LayerNorm -> bf16 hi/lo
__global__ void __launch_bounds__(256) ln_kernel(
    const float* __restrict__ x, const float* __restrict__ w,
    const float* __restrict__ b,
    __nv_bfloat16* __restrict__ hi, __nv_bfloat16* __restrict__ lo)
{
    const int t = blockIdx.x;
    const float4 v = reinterpret_cast<const float4*>(x + (size_t)t * DMODEL)[threadIdx.x];
    float s  = v.x + v.y + v.z + v.w;
    float sq = v.x*v.x + v.y*v.y + v.z*v.z + v.w*v.w;

    __shared__ float sa[8], sb2[8];
    int lane = threadIdx.x & 31, wrp = threadIdx.x >> 5;
    #pragma unroll
    for (int o = 16; o; o >>= 1) {
        s  += __shfl_down_sync(0xffffffffu, s,  o);
        sq += __shfl_down_sync(0xffffffffu, sq, o);
    }
    if (lane == 0) { sa[wrp] = s; sb2[wrp] = sq; }
    __syncthreads();
    if (wrp == 0) {
        s  = (lane < 8) ? sa[lane] : 0.f;
        sq = (lane < 8) ? sb2[lane] : 0.f;
        #pragma unroll
        for (int o = 4; o; o >>= 1) {
            s  += __shfl_down_sync(0xffffffffu, s,  o);
            sq += __shfl_down_sync(0xffffffffu, sq, o);
        }
        if (lane == 0) { sa[0] = s; sb2[0] = sq; }
    }
    __syncthreads();
    const float mu  = sa[0] * (1.f / DMODEL);
    const float var = sb2[0] * (1.f / DMODEL) - mu * mu;
    const float inv = rsqrtf(var + 1e-5f);

    const float4 wv = reinterpret_cast<const float4*>(w)[threadIdx.x];
    const float4 bv = reinterpret_cast<const float4*>(b)[threadIdx.x];
    float4 o4;
    o4.x = (v.x - mu) * inv * wv.x + bv.x;
    o4.y = (v.y - mu) * inv * wv.y + bv.y;
    o4.z = (v.z - mu) * inv * wv.z + bv.z;
    o4.w = (v.w - mu) * inv * wv.w + bv.w;

    __nv_bfloat162 h0 = __floats2bfloat162_rn(o4.x, o4.y);
    __nv_bfloat162 h1 = __floats2bfloat162_rn(o4.z, o4.w);
    __nv_bfloat162 l0 = __floats2bfloat162_rn(o4.x - __bfloat162float(h0.x),
                                              o4.y - __bfloat162float(h0.y));
    __nv_bfloat162 l1 = __floats2bfloat162_rn(o4.z - __bfloat162float(h1.x),
                                              o4.w - __bfloat162float(h1.y));
    const size_t base2 = ((size_t)t * DMODEL) / 2 + threadIdx.x * 2;
    reinterpret_cast<__nv_bfloat162*>(hi)[base2]     = h0;
    reinterpret_cast<__nv_bfloat162*>(hi)[base2 + 1] = h1;
    reinterpret_cast<__nv_bfloat162*>(lo)[base2]     = l0;
    reinterpret_cast<__nv_bfloat162*>(lo)[base2 + 1] = l1;
}

#define BM  128
#define BKT 16
#define APAD 4

template<int MODE, bool ACOL, int TN>
__global__ void __launch_bounds__(256) gemm_k(
    const float* __restrict__ A, int lda, const float* __restrict__ B,
    float* __restrict__ C, float* __restrict__ C2,
    const float* __restrict__ bias, const float* __restrict__ resid,
    int M, int N, int K, int kSplitLen)
{
    constexpr int BN = TN * 16;
    __shared__ __align__(16) float As[2][BKT][BM + APAD];
    __shared__ __align__(16) float Bs[2][BKT][BN];

    const int tid = threadIdx.x;
    const int n0 = blockIdx.x * BN;
    const int m0 = blockIdx.y * BM;
    const int kBase = blockIdx.z * kSplitLen;
    const int nT = kSplitLen / BKT;
    const int tm = tid >> 4, tn = tid & 15;

    unsigned long long acc[TN][4];
    #pragma unroll
    for (int j = 0; j < TN; j++)
        #pragma unroll
        for (int p = 0; p < 4; p++) acc[j][p] = 0ull;

    float4 ar0, ar1, br0, br1;

#define LOAD_A(k0_) do {                                                        \
    if (ACOL) {                                                                 \
        const int m4 = tid & 31, kr = tid >> 5;                                 \
        ar0 = *(const float4*)(A + (size_t)((k0_) + kr)     * lda + m0 + m4*4); \
        ar1 = *(const float4*)(A + (size_t)((k0_) + kr + 8) * lda + m0 + m4*4); \
    } else {                                                                    \
        const int rr = tid >> 2, kq = tid & 3;                                  \
        ar0 = *(const float4*)(A + (size_t)(m0 + rr)      * lda + (k0_) + kq*4);\
        ar1 = *(const float4*)(A + (size_t)(m0 + rr + 64) * lda + (k0_) + kq*4);\
    } } while (0)

#define LOAD_B(k0_) do {                                                        \
    if (TN == 8) {                                                              \
        const int nr = tid >> 1, kq = tid & 1;                                  \
        if (n0 + nr < N) {                                                      \
            const float* bp = B + (size_t)(n0 + nr) * K + (k0_) + kq * 8;       \
            br0 = *(const float4*)(bp);                                         \
            br1 = *(const float4*)(bp + 4);                                     \
        } else { br0 = make_float4(0,0,0,0); br1 = br0; }                       \
    } else {                                                                    \
        const int nr = tid >> 2, kq = tid & 3;                                  \
        br0 = (n0 + nr < N)                                                     \
            ? *(const float4*)(B + (size_t)(n0 + nr) * K + (k0_) + kq*4)        \
            : make_float4(0,0,0,0);                                             \
    } } while (0)

#define STORE_A(st_) do {                                                       \
    if (ACOL) {                                                                 \
        const int m4 = tid & 31, kr = tid >> 5;                                 \
        *(float4*)&As[st_][kr  ][m4*4] = ar0;                                   \
        *(float4*)&As[st_][kr+8][m4*4] = ar1;                                   \
    } else {                                                                    \
        const int rr = tid >> 2, kq = tid & 3;                                  \
        As[st_][kq*4+0][rr]    = ar0.x; As[st_][kq*4+1][rr]    = ar0.y;         \
        As[st_][kq*4+2][rr]    = ar0.z; As[st_][kq*4+3][rr]    = ar0.w;         \
        As[st_][kq*4+0][rr+64] = ar1.x; As[st_][kq*4+1][rr+64] = ar1.y;         \
        As[st_][kq*4+2][rr+64] = ar1.z; As[st_][kq*4+3][rr+64] = ar1.w;         \
    } } while (0)

#define STORE_B(st_) do {                                                       \
    if (TN == 8) {                                                              \
        const int nr = tid >> 1, kq = tid & 1;                                  \
        Bs[st_][kq*8+0][nr] = br0.x; Bs[st_][kq*8+1][nr] = br0.y;               \
        Bs[st_][kq*8+2][nr] = br0.z; Bs[st_][kq*8+3][nr] = br0.w;               \
        Bs[st_][kq*8+4][nr] = br1.x; Bs[st_][kq*8+5][nr] = br1.y;               \
        Bs[st_][kq*8+6][nr] = br1.z; Bs[st_][kq*8+7][nr] = br1.w;               \
    } else {                                                                    \
        const int nr = tid >> 2, kq = tid & 3;                                  \
        Bs[st_][kq*4+0][nr] = br0.x; Bs[st_][kq*4+1][nr] = br0.y;               \
        Bs[st_][kq*4+2][nr] = br0.z; Bs[st_][kq*4+3][nr] = br0.w;               \
    } } while (0)

#define COMPUTE(st_) do {                                                       \
    _Pragma("unroll")                                                           \
    for (int kk = 0; kk < BKT; kk++) {                                          \
        const float* arow = &As[st_][kk][tm * 8];                               \
        ulonglong2 a01 = *(const ulonglong2*)(arow);                            \
        ulonglong2 a23 = *(const ulonglong2*)(arow + 4);                        \
        unsigned long long apk[4] = {a01.x, a01.y, a23.x, a23.y};               \
        float bv[TN];                                                           \
        *(float4*)&bv[0] = *(const float4*)&Bs[st_][kk][tn * TN];               \
        if (TN == 8)                                                            \
            *(float4*)&bv[4] = *(const float4*)&Bs[st_][kk][tn * TN + 4];       \
        _Pragma("unroll")                                                       \
        for (int j = 0; j < TN; j++) {                                          \
            unsigned long long bd = dup2(bv[j]);                                \
            _Pragma("unroll")                                                   \
            for (int p = 0; p < 4; p++) fma2(acc[j][p], apk[p], bd);            \
        }                                                                       \
    } } while (0)

    int k0 = kBase;
    LOAD_A(k0); LOAD_B(k0);
    STORE_A(0); STORE_B(0);
    __syncthreads();
    int st = 0;
    for (int t = 0; t < nT; t++) {
        const bool more = (t + 1 < nT);
        if (more) { LOAD_A(k0 + BKT); LOAD_B(k0 + BKT); }
        COMPUTE(st);
        if (more) {
            STORE_A(st ^ 1); STORE_B(st ^ 1);
            __syncthreads();
            st ^= 1; k0 += BKT;
        }
    }

#undef LOAD_A
#undef LOAD_B
#undef STORE_A
#undef STORE_B
#undef COMPUTE

    #pragma unroll
    for (int j = 0; j < TN; j++) {
        const int n = n0 + tn * TN + j;
        if (n >= N) continue;
        #pragma unroll
        for (int p = 0; p < 4; p++) {
            const int m = m0 + tm * 8 + 2 * p;
            float2 v = *reinterpret_cast<float2*>(&acc[j][p]);
            if (MODE == 0) {
                float* dst = C + (size_t)blockIdx.z * M * N + (size_t)m * N + n;
                dst[0] = v.x; dst[N] = v.y;
            } else if (MODE == 2) {
                const float bx = bias[n];
                float a0 = v.x + bx, a1 = v.y + bx;
                a0 = (a0 > 20.f) ? a0 : log1pf(expf(a0));
                a1 = (a1 > 20.f) ? a1 : log1pf(expf(a1));
                *reinterpret_cast<float2*>(C + (size_t)n * M + m) = make_float2(a0, a1);
            }
        }
    }
}

__global__ void __launch_bounds__(256) reduce_k(
    const float* __restrict__ part, float* __restrict__ out, int n)
{
    const int i = blockIdx.x * 256 + threadIdx.x;
    if (i < n) {
        float s = 0.f;
        #pragma unroll
        for (int z = 0; z < SPLITK; z++) s += part[(size_t)z * n + i];
        out[i] = s;
    }
}

__global__ void __launch_bounds__(256) conv_kernel(
    const float* __restrict__ xt, const float* __restrict__ cw,
    const float* __restrict__ cb, float* __restrict__ xct)
{
    const int row = blockIdx.x;
    const int d = row >> 1, b = row & 1;
    const size_t base = (size_t)d * NTOK + b * 1024;

    __shared__ float s[1024 + 3];
    const int tid = threadIdx.x;
    const float4 v = reinterpret_cast<const float4*>(xt + base)[tid];
    s[3 + tid*4 + 0] = v.x; s[3 + tid*4 + 1] = v.y;
    s[3 + tid*4 + 2] = v.z; s[3 + tid*4 + 3] = v.w;
    if (tid == 0) { s[0] = 0.f; s[1] = 0.f; s[2] = 0.f; }
    __syncthreads();

    const float w0 = cw[d*4+0], w1 = cw[d*4+1], w2 = cw[d*4+2], w3 = cw[d*4+3];
    const float bs = cb[d];
    float4 o;
    #pragma unroll
    for (int i = 0; i < 4; i++) {
        const int l = tid * 4 + i;
        float r = bs + w0*s[l] + w1*s[l+1] + w2*s[l+2] + w3*s[l+3];
        r = r / (1.f + __expf(-r));
        ((float*)&o)[i] = r;
    }
    reinterpret_cast<float4*>(xct + base)[tid] = o;
}

// scan: broadcast streams (dt/xc/z) via float4 every 4 steps; B/C token-major
__global__ void __launch_bounds__(256) scan_kernel(
    const float* __restrict__ xdbl, const float* __restrict__ dtt,
    const float* __restrict__ xct,  const float* __restrict__ zt,
    const float* __restrict__ A_log, const float* __restrict__ Dp,
    float* __restrict__ yt)
{
    const int gt = blockIdx.x * blockDim.x + threadIdx.x;
    const int g = gt >> 4, s = gt & 15;
    const int b = g >> 11, d = g & 2047;

    const float Ac = -expf(A_log[d * DSTATE + s]);
    const float Dd = Dp[d];
    const size_t base = (size_t)d * NTOK + b * 1024;
    const float4* __restrict__ dtp = reinterpret_cast<const float4*>(dtt + base);
    const float4* __restrict__ xcp = reinterpret_cast<const float4*>(xct + base);
    const float4* __restrict__ zp  = reinterpret_cast<const float4*>(zt  + base);
    float* __restrict__ yp = yt + (size_t)b * 1024 * DINNER + d;
    const float* __restrict__ xd = xdbl + (size_t)(b * 1024) * XDBL_N;

    float h = 0.f;
    for (int q = 0; q < 256; q++) {
        const float4 d4 = dtp[q];
        const float4 x4 = xcp[q];
        const float4 z4 = zp[q];
        #pragma unroll
        for (int i = 0; i < 4; i++) {
            const int t = q * 4 + i;
            const float dt  = (&d4.x)[i];
            const float xc  = (&x4.x)[i];
            const float bsv = xd[t * XDBL_N + DTRANK + s];
            const float csv = xd[t * XDBL_N + DTRANK + DSTATE + s];
            const float da = __expf(dt * Ac);
            h = fmaf(da, h, dt * bsv * xc);
            float p = h * csv;
            p += __shfl_xor_sync(0xffffffffu, p, 8, 16);
            p += __shfl_xor_sync(0xffffffffu, p, 4, 16);
            p += __shfl_xor_sync(0xffffffffu, p, 2, 16);
            p += __shfl_xor_sync(0xffffffffu, p, 1, 16);
            if (s == 0) {
                const float zv = (&z4.x)[i];
                const float gate = zv / (1.f + __expf(-zv));
                yp[(size_t)t * DINNER] = (p + xc * Dd) * gate;
            }
        }
    }
}

// ---------------------------------------------------------------------------
// host
// ---------------------------------------------------------------------------
extern "C" void kernel_launch(void* const* d_in, const int* in_sizes, int n_in,
                              void* d_out, int out_size)
{
    const float* x        = (const float*)d_in[0];
    const float* ln_w     = (const float*)d_in[1];
    const float* ln_b     = (const float*)d_in[2];
    const float* in_w     = (const float*)d_in[3];
    const float* conv_w   = (const float*)d_in[4];
    const float* conv_b   = (const float*)d_in[5];
    const float* xproj_w  = (const float*)d_in[6];
    const float* dtproj_w = (const float*)d_in[7];
    const float* dtproj_b = (const float*)d_in[8];
    const float* A_log    = (const float*)d_in[9];
    const float* Dp       = (const float*)d_in[10];
    const float* out_w    = (const float*)d_in[11];
    float* out = (float*)d_out;

    float *xt, *zt, *xct, *dtt, *yt, *xdbl, *xdblp, *opart;
    cudaGetSymbolAddress((void**)&xt,    g_xt);
    cudaGetSymbolAddress((void**)&zt,    g_zt);
    cudaGetSymbolAddress((void**)&xct,   g_xct);
    cudaGetSymbolAddress((void**)&dtt,   g_dtt);
    cudaGetSymbolAddress((void**)&yt,    g_yt);
    cudaGetSymbolAddress((void**)&xdbl,  g_xdbl);
    cudaGetSymbolAddress((void**)&xdblp, g_xdbl_part);
    cudaGetSymbolAddress((void**)&opart, g_opart);

    __nv_bfloat16 *h_hi, *h_lo, *iw_hi, *iw_lo, *yt_hi, *yt_lo, *ow_hi, *ow_lo;
    cudaGetSymbolAddress((void**)&h_hi,  g_h_hi);
    cudaGetSymbolAddress((void**)&h_lo,  g_h_lo);
    cudaGetSymbolAddress((void**)&iw_hi, g_iw_hi);
    cudaGetSymbolAddress((void**)&iw_lo, g_iw_lo);
    cudaGetSymbolAddress((void**)&yt_hi, g_yt_hi);
    cudaGetSymbolAddress((void**)&yt_lo, g_yt_lo);
    cudaGetSymbolAddress((void**)&ow_hi, g_ow_hi);
    cudaGetSymbolAddress((void**)&ow_lo, g_ow_lo);

    cudaFuncSetAttribute(mm_gemm<0>, cudaFuncAttributeMaxDynamicSharedMemorySize,
                         MM_SMEM);
    cudaFuncSetAttribute(mm_gemm<1>, cudaFuncAttributeMaxDynamicSharedMemorySize,
                         MM_SMEM);

    // 1-2. weight splits first (keeps mm0 in the profiled slot)
    cvt_split<<<(DMODEL * DINNER / 4) / 256, 256>>>(out_w, ow_hi, ow_lo,
                                                    DMODEL * DINNER / 4);
    cvt_split<<<(2 * DINNER * DMODEL / 4) / 256, 256>>>(in_w, iw_hi, iw_lo,
                                                        2 * DINNER * DMODEL / 4);
    // 3. layernorm -> bf16 hi/lo
    ln_kernel<<<NTOK, 256>>>(x, ln_w, ln_b, h_hi, h_lo);

    // 4. in_proj: M=2048, N=4096, K=1024 -> xt/zt channel-major
    mm_gemm<0><<<dim3(4096 / 128, NTOK / 128, 1), 256, MM_SMEM>>>(
        h_hi, h_lo, DMODEL, iw_hi, iw_lo, DMODEL, DMODEL / KC, xt, zt, nullptr);

    // 5. depthwise conv + silu
    conv_kernel<<<DINNER * 2, 256>>>(xt, conv_w, conv_b, xct);

    // 6. x_proj (fp32 split-K)
    gemm_k<0, true, 4><<<dim3(2, NTOK / BM, SPLITK), 256>>>(
        xct, NTOK, xproj_w, xdblp, nullptr, nullptr, nullptr,
        NTOK, XDBL_N, DINNER, DINNER / SPLITK);
    reduce_k<<<(NTOK * XDBL_N + 255) / 256, 256>>>(xdblp, xdbl, NTOK * XDBL_N);

    // 7. dt = softplus(...) (fp32)
    gemm_k<2, false, 8><<<dim3(DINNER / 128, NTOK / BM, 1), 256>>>(
        xdbl, XDBL_N, dtproj_w, dtt, nullptr, dtproj_b, nullptr,
        NTOK, DINNER, DTRANK, DTRANK);

    // 8. selective scan -> yt fp32 token-major
    scan_kernel<<<(2 * DINNER * DSTATE) / 256, 256>>>(
        xdbl, dtt, xct, zt, A_log, Dp, yt);

    // 9. split yt
    cvt_split<<<(NTOK * DINNER / 4) / 256, 256>>>(yt, yt_hi, yt_lo,
                                                  NTOK * DINNER / 4);

    // 10. out_proj split-K=2 partials: 256 CTAs = full wave
    mm_gemm<1><<<dim3(DMODEL / 128, NTOK / 128, 2), 256, MM_SMEM>>>(
        yt_hi, yt_lo, DINNER, ow_hi, ow_lo, DINNER, (DINNER / KC) / 2,
        opart, nullptr, nullptr);

    // 11. reduce partials + residual
    add_out<<<(NTOK * DMODEL / 4) / 256, 256>>>(opart, x, out);
}

// round 14
// speedup vs baseline: 1.4244x; 1.0039x over previous
#include <cuda_runtime.h>
#include <cuda_bf16.h>
#include <cstdint>

// ---------------------------------------------------------------------------
// MambaBlock on GB300 (plain sm_103 -> mma.sync path).  R13 baseline (732us)
// + single subsystem change: out_proj switched to SINGLE-PASS tf32
// mma.sync.m16n8k8 reading fp32 yt/out_w directly (cvt_split(out_w) and
// cvt_split(yt) removed).  in_proj stays 3-pass bf16-split.
// ---------------------------------------------------------------------------

#define NTOK    2048
#define DMODEL  1024
#define DINNER  2048
#define DSTATE  16
#define DTRANK  64
#define XDBL_N  96
#define SPLITK  8

__device__ float g_xt  [DINNER * NTOK];
__device__ float g_zt  [DINNER * NTOK];
__device__ float g_xct [DINNER * NTOK];
__device__ float g_dtt [DINNER * NTOK];
__device__ float g_yt  [NTOK * DINNER];        // token-major fp32
__device__ float g_xdbl[NTOK * XDBL_N];
__device__ float g_xdbl_part[SPLITK * NTOK * XDBL_N];
__device__ float g_opart[2 * NTOK * DMODEL];   // out_proj split-K partials

// pre-split bf16 hi/lo (in_proj only)
__device__ __nv_bfloat16 g_h_hi [NTOK * DMODEL];
__device__ __nv_bfloat16 g_h_lo [NTOK * DMODEL];
__device__ __nv_bfloat16 g_iw_hi[2 * DINNER * DMODEL];
__device__ __nv_bfloat16 g_iw_lo[2 * DINNER * DMODEL];

// =========================== helpers =======================================
__device__ __forceinline__ uint32_t smem_u32(const void* p) {
    uint32_t a;
    asm("{ .reg .u64 t; cvta.to.shared.u64 t, %1; cvt.u32.u64 %0, t; }"
        : "=r"(a) : "l"(p));
    return a;
}

__device__ __forceinline__ void ldm_x4(uint32_t* r, uint32_t addr) {
    asm volatile("ldmatrix.sync.aligned.m8n8.x4.shared.b16 {%0,%1,%2,%3}, [%4];"
        : "=r"(r[0]), "=r"(r[1]), "=r"(r[2]), "=r"(r[3]) : "r"(addr));
}

__device__ __forceinline__ void mma_bf16(float* c, const uint32_t* a,
                                         const uint32_t* b) {
    asm volatile(
        "mma.sync.aligned.m16n8k16.row.col.f32.bf16.bf16.f32 "
        "{%0,%1,%2,%3}, {%4,%5,%6,%7}, {%8,%9}, {%0,%1,%2,%3};"
        : "+f"(c[0]), "+f"(c[1]), "+f"(c[2]), "+f"(c[3])
        : "r"(a[0]), "r"(a[1]), "r"(a[2]), "r"(a[3]), "r"(b[0]), "r"(b[1]));
}

__device__ __forceinline__ void mma_tf32(float* c, const uint32_t* a,
                                         const uint32_t* b) {
    asm volatile(
        "mma.sync.aligned.m16n8k8.row.col.f32.tf32.tf32.f32 "
        "{%0,%1,%2,%3}, {%4,%5,%6,%7}, {%8,%9}, {%0,%1,%2,%3};"
        : "+f"(c[0]), "+f"(c[1]), "+f"(c[2]), "+f"(c[3])
        : "r"(a[0]), "r"(a[1]), "r"(a[2]), "r"(a[3]), "r"(b[0]), "r"(b[1]));
}

__device__ __forceinline__ uint32_t to_tf32(float x) {
    uint32_t u;
    asm("cvt.rna.tf32.f32 %0, %1;" : "=r"(u) : "f"(x));
    return u;
}

#define CP16(dst, src) \
    asm volatile("cp.async.cg.shared.global [%0], [%1], 16;" \
                 :: "r"(dst), "l"(src))
#define CP_COMMIT() asm volatile("cp.async.commit_group;" ::: "memory")

// fp32 -> bf16 hi/lo split (elementwise)
__global__ void __launch_bounds__(256) cvt_split(
    const float* __restrict__ src, __nv_bfloat16* __restrict__ hi,
    __nv_bfloat16* __restrict__ lo, int n4)
{
    const int i = blockIdx.x * 256 + threadIdx.x;
    if (i >= n4) return;
    const float4 v = reinterpret_cast<const float4*>(src)[i];
    __nv_bfloat162 h0 = __floats2bfloat162_rn(v.x, v.y);
    __nv_bfloat162 h1 = __floats2bfloat162_rn(v.z, v.w);
    __nv_bfloat162 l0 = __floats2bfloat162_rn(v.x - __bfloat162float(h0.x),
                                              v.y - __bfloat162float(h0.y));
    __nv_bfloat162 l1 = __floats2bfloat162_rn(v.z - __bfloat162float(h1.x),
                                              v.w - __bfloat162float(h1.y));
    reinterpret_cast<__nv_bfloat162*>(hi)[2*i]   = h0;
    reinterpret_cast<__nv_bfloat162*>(hi)[2*i+1] = h1;
    reinterpret_cast<__nv_bfloat162*>(lo)[2*i]   = l0;
    reinterpret_cast<__nv_bfloat162*>(lo)[2*i+1] = l1;
}

// ---------------------------------------------------------------------------
// bf16-split tensor GEMM (in_proj): CTA 128x128, 256 threads, 8 warps =
// 2(m) x 4(n), warp 64x32, Kc=32/stage, double-buffered cp.async.
// Channel-major store via smem transpose; n<2048 -> out0 else out1.
// ---------------------------------------------------------------------------
#define KC 32
#define STG    40960
#define R_A_LO 10240
#define R_B_HI 20480
#define R_B_LO 30720
#define MM_SMEM 81920

__global__ void __launch_bounds__(256, 2) mm_gemm0(
    const __nv_bfloat16* __restrict__ Ahi, const __nv_bfloat16* __restrict__ Alo,
    int lda,
    const __nv_bfloat16* __restrict__ Bhi, const __nv_bfloat16* __restrict__ Blo,
    int ldb, int nchunk,
    float* __restrict__ out0, float* __restrict__ out1)
{
    extern __shared__ char smem_dyn[];
    const uint32_t sbase = smem_u32(smem_dyn);
    const int tid  = threadIdx.x;
    const int lane = tid & 31;
    const int w    = tid >> 5;
    const int wm   = w >> 2;
    const int wn   = w & 3;
    const int n0   = blockIdx.x * 128;
    const int m0   = blockIdx.y * 128;

    const int lrow  = tid >> 1;
    const int lhalf = (tid & 1) * 16;

    const int a_row  = wm * 64 + (lane & 15);
    const int a_coff = ((lane & 16) ? 16 : 0);
    const int b_row  = wn * 32 + ((lane >> 4) & 1) * 8 + (lane & 7);
    const int b_coff = ((lane & 8) ? 16 : 0);

    float acc[4][4][4];
    #pragma unroll
    for (int i = 0; i < 4; i++)
        #pragma unroll
        for (int j = 0; j < 4; j++)
            #pragma unroll
            for (int p = 0; p < 4; p++) acc[i][j][p] = 0.f;

#define ISSUE(c_, buf_) do {                                                    \
    const int kc0 = (c_) * KC;                                                  \
    const uint32_t sd = sbase + (buf_) * STG + lrow * 80 + lhalf * 2;           \
    const __nv_bfloat16* a0 = Ahi + (size_t)(m0 + lrow) * lda + kc0 + lhalf;    \
    const __nv_bfloat16* a1 = Alo + (size_t)(m0 + lrow) * lda + kc0 + lhalf;    \
    const __nv_bfloat16* b0 = Bhi + (size_t)(n0 + lrow) * ldb + kc0 + lhalf;    \
    const __nv_bfloat16* b1 = Blo + (size_t)(n0 + lrow) * ldb + kc0 + lhalf;    \
    CP16(sd,               a0);  CP16(sd + 16,          a0 + 8);                \
    CP16(sd + R_A_LO,      a1);  CP16(sd + R_A_LO + 16, a1 + 8);                \
    CP16(sd + R_B_HI,      b0);  CP16(sd + R_B_HI + 16, b0 + 8);                \
    CP16(sd + R_B_LO,      b1);  CP16(sd + R_B_LO + 16, b1 + 8);                \
    CP_COMMIT();                                                                \
    } while (0)

#define COMPUTE(buf_) do {                                                      \
    const uint32_t sa = sbase + (buf_) * STG;                                   \
    _Pragma("unroll")                                                           \
    for (int s = 0; s < 2; s++) {                                               \
        uint32_t Ah[4][4], Al[4][4], Bh[2][4], Bl[2][4];                        \
        _Pragma("unroll")                                                       \
        for (int mf = 0; mf < 4; mf++) {                                        \
            const uint32_t ar = sa + (a_row + mf * 16) * 80 + a_coff + s * 32;  \
            ldm_x4(Ah[mf], ar);                                                 \
            ldm_x4(Al[mf], ar + R_A_LO);                                        \
        }                                                                       \
        _Pragma("unroll")                                                       \
        for (int np = 0; np < 2; np++) {                                        \
            const uint32_t br = sa + R_B_HI + (b_row + np * 16) * 80            \
                                + b_coff + s * 32;                              \
            ldm_x4(Bh[np], br);                                                 \
            ldm_x4(Bl[np], br + (R_B_LO - R_B_HI));                             \
        }                                                                       \
        _Pragma("unroll")                                                       \
        for (int mf = 0; mf < 4; mf++)                                          \
            _Pragma("unroll")                                                   \
            for (int nf = 0; nf < 4; nf++) {                                    \
                const uint32_t* bh = &Bh[nf >> 1][(nf & 1) * 2];                \
                const uint32_t* bl = &Bl[nf >> 1][(nf & 1) * 2];                \
                mma_bf16(acc[mf][nf], Ah[mf], bh);                              \
                mma_bf16(acc[mf][nf], Ah[mf], bl);                              \
                mma_bf16(acc[mf][nf], Al[mf], bh);                              \
            }                                                                   \
    } } while (0)

    ISSUE(0, 0);
    for (int c = 0; c < nchunk; c++) {
        const int buf = c & 1;
        if (c + 1 < nchunk) {
            ISSUE(c + 1, buf ^ 1);
            asm volatile("cp.async.wait_group 1;" ::: "memory");
        } else {
            asm volatile("cp.async.wait_group 0;" ::: "memory");
        }
        __syncthreads();
        COMPUTE(buf);
        __syncthreads();
    }

#undef ISSUE
#undef COMPUTE

    const int rg = lane >> 2;
    const int cp = (lane & 3) * 2;

    float* T = reinterpret_cast<float*>(smem_dyn);
    #pragma unroll
    for (int mf = 0; mf < 4; mf++)
        #pragma unroll
        for (int nf = 0; nf < 4; nf++) {
            const int m = wm * 64 + mf * 16 + rg;
            const int n = wn * 32 + nf * 8 + cp;
            T[(n    ) * 132 + m    ] = acc[mf][nf][0];
            T[(n + 1) * 132 + m    ] = acc[mf][nf][1];
            T[(n    ) * 132 + m + 8] = acc[mf][nf][2];
            T[(n + 1) * 132 + m + 8] = acc[mf][nf][3];
        }
    __syncthreads();
    float* ob; int nc0;
    if (n0 < 2048) { ob = out0; nc0 = n0; }
    else           { ob = out1; nc0 = n0 - 2048; }
    const int n  = tid >> 1;
    const int mh = (tid & 1) * 64;
    const float4* src = reinterpret_cast<const float4*>(&T[n * 132 + mh]);
    float4* dst = reinterpret_cast<float4*>(
        ob + (size_t)(nc0 + n) * NTOK + m0 + mh);
    #pragma unroll
    for (int j = 0; j < 16; j++) dst[j] = src[j];
}

// ---------------------------------------------------------------------------
// tf32 single-pass GEMM (out_proj): D[m][n] = sum_k A[m][k]*B[n][k], fp32 in.
// CTA 128x128, 256 thr, 8 warps 2(m) x 4(n), warp 64x32, Kc=32, 2 stages.
// Split-K partial: out0[z*NTOK*DMODEL + m*DMODEL + n] = D.
// Stage: As[128][36] f32 @0 (18432B), Bs[128][36] @18432; stage 36864B.
// ---------------------------------------------------------------------------
#define TFSTG 36864
#define TF_B  18432
#define TF_SMEM (2 * TFSTG)

__global__ void __launch_bounds__(256, 2) tf_gemm(
    const float* __restrict__ A, int lda,
    const float* __restrict__ B, int ldb, int nchunk,
    float* __restrict__ out0)
{
    extern __shared__ char smem_dyn[];
    float* Sf = reinterpret_cast<float*>(smem_dyn);
    const uint32_t sbase = smem_u32(smem_dyn);
    const int tid  = threadIdx.x;
    const int lane = tid & 31;
    const int w    = tid >> 5;
    const int wm   = w >> 2;             // 0..1
    const int wn   = w & 3;              // 0..3
    const int n0   = blockIdx.x * 128;
    const int m0   = blockIdx.y * 128;
    const int kbase = blockIdx.z * nchunk;

    const int lrow  = tid >> 1;          // 0..127
    const int lhalf = (tid & 1) * 16;    // floats

    const int g = lane >> 2;             // 0..7
    const int t = lane & 3;              // 0..3

    float acc[4][4][4];
    #pragma unroll
    for (int i = 0; i < 4; i++)
        #pragma unroll
        for (int j = 0; j < 4; j++)
            #pragma unroll
            for (int p = 0; p < 4; p++) acc[i][j][p] = 0.f;

#define TISSUE(c_, buf_) do {                                                   \
    const int kc0 = (c_) * KC;                                                  \
    const uint32_t sd = sbase + (buf_) * TFSTG + (lrow * 36 + lhalf) * 4;       \
    const float* ag = A + (size_t)(m0 + lrow) * lda + kc0 + lhalf;              \
    const float* bg = B + (size_t)(n0 + lrow) * ldb + kc0 + lhalf;              \
    CP16(sd,      ag);      CP16(sd + 16,        ag + 4);                       \
    CP16(sd + 32, ag + 8);  CP16(sd + 48,        ag + 12);                      \
    CP16(sd + TF_B,      bg);     CP16(sd + TF_B + 16, bg + 4);                 \
    CP16(sd + TF_B + 32, bg + 8); CP16(sd + TF_B + 48, bg + 12);                \
    CP_COMMIT();                                                                \
    } while (0)

#define TCOMPUTE(buf_) do {                                                     \
    float* As = Sf + (buf_) * (TFSTG / 4);                                      \
    float* Bs = As + (TF_B / 4);                                                \
    _Pragma("unroll")                                                           \
    for (int ks = 0; ks < 4; ks++) {                                            \
        uint32_t Af[4][4], Bf[4][2];                                            \
        _Pragma("unroll")                                                       \
        for (int mf = 0; mf < 4; mf++) {                                        \
            const int r = wm * 64 + mf * 16 + g;                                \
            const int c = ks * 8 + t;                                           \
            Af[mf][0] = to_tf32(As[(r    ) * 36 + c    ]);                      \
            Af[mf][1] = to_tf32(As[(r + 8) * 36 + c    ]);                      \
            Af[mf][2] = to_tf32(As[(r    ) * 36 + c + 4]);                      \
            Af[mf][3] = to_tf32(As[(r + 8) * 36 + c + 4]);                      \
        }                                                                       \
        _Pragma("unroll")                                                       \
        for (int nf = 0; nf < 4; nf++) {                                        \
            const int r = wn * 32 + nf * 8 + g;                                 \
            const int c = ks * 8 + t;                                           \
            Bf[nf][0] = to_tf32(Bs[r * 36 + c    ]);                            \
            Bf[nf][1] = to_tf32(Bs[r * 36 + c + 4]);                            \
        }                                                                       \
        _Pragma("unroll")                                                       \
        for (int mf = 0; mf < 4; mf++)                                          \
            _Pragma("unroll")                                                   \
            for (int nf = 0; nf < 4; nf++)                                      \
                mma_tf32(acc[mf][nf], Af[mf], Bf[nf]);                          \
    } } while (0)

    TISSUE(kbase, 0);
    for (int c = 0; c < nchunk; c++) {
        const int buf = c & 1;
        if (c + 1 < nchunk) {
            TISSUE(kbase + c + 1, buf ^ 1);
            asm volatile("cp.async.wait_group 1;" ::: "memory");
        } else {
            asm volatile("cp.async.wait_group 0;" ::: "memory");
        }
        __syncthreads();
        TCOMPUTE(buf);
        __syncthreads();
    }

#undef TISSUE
#undef TCOMPUTE

    const int rg = lane >> 2;
    const int cp = (lane & 3) * 2;
    float* part = out0 + (size_t)blockIdx.z * NTOK * DMODEL;
    #pragma unroll
    for (int mf = 0; mf < 4; mf++)
        #pragma unroll
        for (int nf = 0; nf < 4; nf++) {
            const int m = m0 + wm * 64 + mf * 16 + rg;
            const int n = n0 + wn * 32 + nf * 8 + cp;
            *reinterpret_cast<float2*>(part + (size_t)m * DMODEL + n) =
                make_float2(acc[mf][nf][0], acc[mf][nf][1]);
            *reinterpret_cast<float2*>(part + (size_t)(m + 8) * DMODEL + n) =
                make_float2(acc[mf][nf][2], acc[mf][nf][3]);
        }
}

// out = part0 + part1 + x   (split-K reduce + residual)
__global__ void __launch_bounds__(256) add_out(
    const float* __restrict__ part, const float* __restrict__ x,
    float* __restrict__ out)
{
    const int i = blockIdx.x * 256 + threadIdx.x;
    const float4 a = reinterpret_cast<const float4*>(part)[i];
    const float4 b = reinterpret_cast<const float4*>(part + NTOK * DMODEL)[i];
    const float4 c = reinterpret_cast<const float4*>(x)[i];
    float4 o;
    o.x = a.x + b.x + c.x; o.y = a.y + b.y + c.y;
    o.z = a.z + b.z + c.z; o.w = a.w + b.w + c.w;
    reinterpret_cast<float4*>(out)[i] = o;
}

// ============================ fp32 kernels =================================
__device__ __forceinline__ unsigned long long dup2(float x) {
    unsigned long long r;
    asm("mov.b64 %0, {%1, %1};" : "=l"(r) : "f"(x));
    return r;
}
__device__ __forceinline__ void fma2(unsigned long long& d,
                                     unsigned long long a,
                                     unsigned long long b) {
    asm("fma.rn.f32x2 %0, %1, %2, %0;" : "+l"(d) : "l"(a), "l"(b));
}

// LayerNorm -> bf16 hi/lo
__global__ void __launch_bounds__(256) ln_kernel(
    const float* __restrict__ x, const float* __restrict__ w,
    const float* __restrict__ b,
    __nv_bfloat16* __restrict__ hi, __nv_bfloat16* __restrict__ lo)
{
    const int tkn = blockIdx.x;
    const float4 v = reinterpret_cast<const float4*>(x + (size_t)tkn * DMODEL)[threadIdx.x];
    float s  = v.x + v.y + v.z + v.w;
    float sq = v.x*v.x + v.y*v.y + v.z*v.z + v.w*v.w;

    __shared__ float sa[8], sb2[8];
    int lane = threadIdx.x & 31, wrp = threadIdx.x >> 5;
    #pragma unroll
    for (int o = 16; o; o >>= 1) {
        s  += __shfl_down_sync(0xffffffffu, s,  o);
        sq += __shfl_down_sync(0xffffffffu, sq, o);
    }
    if (lane == 0) { sa[wrp] = s; sb2[wrp] = sq; }
    __syncthreads();
    if (wrp == 0) {
        s  = (lane < 8) ? sa[lane] : 0.f;
        sq = (lane < 8) ? sb2[lane] : 0.f;
        #pragma unroll
        for (int o = 4; o; o >>= 1) {
            s  += __shfl_down_sync(0xffffffffu, s,  o);
            sq += __shfl_down_sync(0xffffffffu, sq, o);
        }
        if (lane == 0) { sa[0] = s; sb2[0] = sq; }
    }
    __syncthreads();
    const float mu  = sa[0] * (1.f / DMODEL);
    const float var = sb2[0] * (1.f / DMODEL) - mu * mu;
    const float inv = rsqrtf(var + 1e-5f);

    const float4 wv = reinterpret_cast<const float4*>(w)[threadIdx.x];
    const float4 bv = reinterpret_cast<const float4*>(b)[threadIdx.x];
    float4 o4;
    o4.x = (v.x - mu) * inv * wv.x + bv.x;
    o4.y = (v.y - mu) * inv * wv.y + bv.y;
    o4.z = (v.z - mu) * inv * wv.z + bv.z;
    o4.w = (v.w - mu) * inv * wv.w + bv.w;

    __nv_bfloat162 h0 = __floats2bfloat162_rn(o4.x, o4.y);
    __nv_bfloat162 h1 = __floats2bfloat162_rn(o4.z, o4.w);
    __nv_bfloat162 l0 = __floats2bfloat162_rn(o4.x - __bfloat162float(h0.x),
                                              o4.y - __bfloat162float(h0.y));
    __nv_bfloat162 l1 = __floats2bfloat162_rn(o4.z - __bfloat162float(h1.x),
                                              o4.w - __bfloat162float(h1.y));
    const size_t base2 = ((size_t)tkn * DMODEL) / 2 + threadIdx.x * 2;
    reinterpret_cast<__nv_bfloat162*>(hi)[base2]     = h0;
    reinterpret_cast<__nv_bfloat162*>(hi)[base2 + 1] = h1;
    reinterpret_cast<__nv_bfloat162*>(lo)[base2]     = l0;
    reinterpret_cast<__nv_bfloat162*>(lo)[base2 + 1] = l1;
}

#define BM  128
#define BKT 16
#define APAD 4

template<int MODE, bool ACOL, int TN>
__global__ void __launch_bounds__(256) gemm_k(
    const float* __restrict__ A, int lda, const float* __restrict__ B,
    float* __restrict__ C, float* __restrict__ C2,
    const float* __restrict__ bias, const float* __restrict__ resid,
    int M, int N, int K, int kSplitLen)
{
    constexpr int BN = TN * 16;
    __shared__ __align__(16) float As[2][BKT][BM + APAD];
    __shared__ __align__(16) float Bs[2][BKT][BN];

    const int tid = threadIdx.x;
    const int n0 = blockIdx.x * BN;
    const int m0 = blockIdx.y * BM;
    const int kBase = blockIdx.z * kSplitLen;
    const int nT = kSplitLen / BKT;
    const int tm = tid >> 4, tn = tid & 15;

    unsigned long long acc[TN][4];
    #pragma unroll
    for (int j = 0; j < TN; j++)
        #pragma unroll
        for (int p = 0; p < 4; p++) acc[j][p] = 0ull;

    float4 ar0, ar1, br0, br1;

#define LOAD_A(k0_) do {                                                        \
    if (ACOL) {                                                                 \
        const int m4 = tid & 31, kr = tid >> 5;                                 \
        ar0 = *(const float4*)(A + (size_t)((k0_) + kr)     * lda + m0 + m4*4); \
        ar1 = *(const float4*)(A + (size_t)((k0_) + kr + 8) * lda + m0 + m4*4); \
    } else {                                                                    \
        const int rr = tid >> 2, kq = tid & 3;                                  \
        ar0 = *(const float4*)(A + (size_t)(m0 + rr)      * lda + (k0_) + kq*4);\
        ar1 = *(const float4*)(A + (size_t)(m0 + rr + 64) * lda + (k0_) + kq*4);\
    } } while (0)

#define LOAD_B(k0_) do {                                                        \
    if (TN == 8) {                                                              \
        const int nr = tid >> 1, kq = tid & 1;                                  \
        if (n0 + nr < N) {                                                      \
            const float* bp = B + (size_t)(n0 + nr) * K + (k0_) + kq * 8;       \
            br0 = *(const float4*)(bp);                                         \
            br1 = *(const float4*)(bp + 4);                                     \
        } else { br0 = make_float4(0,0,0,0); br1 = br0; }                       \
    } else {                                                                    \
        const int nr = tid >> 2, kq = tid & 3;                                  \
        br0 = (n0 + nr < N)                                                     \
            ? *(const float4*)(B + (size_t)(n0 + nr) * K + (k0_) + kq*4)        \
            : make_float4(0,0,0,0);                                             \
    } } while (0)

#define STORE_A(st_) do {                                                       \
    if (ACOL) {                                                                 \
        const int m4 = tid & 31, kr = tid >> 5;                                 \
        *(float4*)&As[st_][kr  ][m4*4] = ar0;                                   \
        *(float4*)&As[st_][kr+8][m4*4] = ar1;                                   \
    } else {                                                                    \
        const int rr = tid >> 2, kq = tid & 3;                                  \
        As[st_][kq*4+0][rr]    = ar0.x; As[st_][kq*4+1][rr]    = ar0.y;         \
        As[st_][kq*4+2][rr]    = ar0.z; As[st_][kq*4+3][rr]    = ar0.w;         \
        As[st_][kq*4+0][rr+64] = ar1.x; As[st_][kq*4+1][rr+64] = ar1.y;         \
        As[st_][kq*4+2][rr+64] = ar1.z; As[st_][kq*4+3][rr+64] = ar1.w;         \
    } } while (0)

#define STORE_B(st_) do {                                                       \
    if (TN == 8) {                                                              \
        const int nr = tid >> 1, kq = tid & 1;                                  \
        Bs[st_][kq*8+0][nr] = br0.x; Bs[st_][kq*8+1][nr] = br0.y;               \
        Bs[st_][kq*8+2][nr] = br0.z; Bs[st_][kq*8+3][nr] = br0.w;               \
        Bs[st_][kq*8+4][nr] = br1.x; Bs[st_][kq*8+5][nr] = br1.y;               \
        Bs[st_][kq*8+6][nr] = br1.z; Bs[st_][kq*8+7][nr] = br1.w;               \
    } else {                                                                    \
        const int nr = tid >> 2, kq = tid & 3;                                  \
        Bs[st_][kq*4+0][nr] = br0.x; Bs[st_][kq*4+1][nr] = br0.y;               \
        Bs[st_][kq*4+2][nr] = br0.z; Bs[st_][kq*4+3][nr] = br0.w;               \
    } } while (0)

#define COMPUTE(st_) do {                                                       \
    _Pragma("unroll")                                                           \
    for (int kk = 0; kk < BKT; kk++) {                                          \
        const float* arow = &As[st_][kk][tm * 8];                               \
        ulonglong2 a01 = *(const ulonglong2*)(arow);                            \
        ulonglong2 a23 = *(const ulonglong2*)(arow + 4);                        \
        unsigned long long apk[4] = {a01.x, a01.y, a23.x, a23.y};               \
        float bv[TN];                                                           \
        *(float4*)&bv[0] = *(const float4*)&Bs[st_][kk][tn * TN];               \
        if (TN == 8)                                                            \
            *(float4*)&bv[4] = *(const float4*)&Bs[st_][kk][tn * TN + 4];       \
        _Pragma("unroll")                                                       \
        for (int j = 0; j < TN; j++) {                                          \
            unsigned long long bd = dup2(bv[j]);                                \
            _Pragma("unroll")                                                   \
            for (int p = 0; p < 4; p++) fma2(acc[j][p], apk[p], bd);            \
        }                                                                       \
    } } while (0)

    int k0 = kBase;
    LOAD_A(k0); LOAD_B(k0);
    STORE_A(0); STORE_B(0);
    __syncthreads();
    int st = 0;
    for (int t2 = 0; t2 < nT; t2++) {
        const bool more = (t2 + 1 < nT);
        if (more) { LOAD_A(k0 + BKT); LOAD_B(k0 + BKT); }
        COMPUTE(st);
        if (more) {
            STORE_A(st ^ 1); STORE_B(st ^ 1);
            __syncthreads();
            st ^= 1; k0 += BKT;
        }
    }

#undef LOAD_A
#undef LOAD_B
#undef STORE_A
#undef STORE_B
#undef COMPUTE

    #pragma unroll
    for (int j = 0; j < TN; j++) {
        const int n = n0 + tn * TN + j;
        if (n >= N) continue;
        #pragma unroll
        for (int p = 0; p < 4; p++) {
            const int m = m0 + tm * 8 + 2 * p;
            float2 v = *reinterpret_cast<float2*>(&acc[j][p]);
            if (MODE == 0) {
                float* dst = C + (size_t)blockIdx.z * M * N + (size_t)m * N + n;
                dst[0] = v.x; dst[N] = v.y;
            } else if (MODE == 2) {
                const float bx = bias[n];
                float a0 = v.x + bx, a1 = v.y + bx;
                a0 = (a0 > 20.f) ? a0 : log1pf(expf(a0));
                a1 = (a1 > 20.f) ? a1 : log1pf(expf(a1));
                *reinterpret_cast<float2*>(C + (size_t)n * M + m) = make_float2(a0, a1);
            }
        }
    }
}

__global__ void __launch_bounds__(256) reduce_k(
    const float* __restrict__ part, float* __restrict__ out, int n)
{
    const int i = blockIdx.x * 256 + threadIdx.x;
    if (i < n) {
        float s = 0.f;
        #pragma unroll
        for (int z = 0; z < SPLITK; z++) s += part[(size_t)z * n + i];
        out[i] = s;
    }
}

__global__ void __launch_bounds__(256) conv_kernel(
    const float* __restrict__ xt, const float* __restrict__ cw,
    const float* __restrict__ cb, float* __restrict__ xct)
{
    const int row = blockIdx.x;
    const int d = row >> 1, b = row & 1;
    const size_t base = (size_t)d * NTOK + b * 1024;

    __shared__ float s[1024 + 3];
    const int tid = threadIdx.x;
    const float4 v = reinterpret_cast<const float4*>(xt + base)[tid];
    s[3 + tid*4 + 0] = v.x; s[3 + tid*4 + 1] = v.y;
    s[3 + tid*4 + 2] = v.z; s[3 + tid*4 + 3] = v.w;
    if (tid == 0) { s[0] = 0.f; s[1] = 0.f; s[2] = 0.f; }
    __syncthreads();

    const float w0 = cw[d*4+0], w1 = cw[d*4+1], w2 = cw[d*4+2], w3 = cw[d*4+3];
    const float bs = cb[d];
    float4 o;
    #pragma unroll
    for (int i = 0; i < 4; i++) {
        const int l = tid * 4 + i;
        float r = bs + w0*s[l] + w1*s[l+1] + w2*s[l+2] + w3*s[l+3];
        r = r / (1.f + __expf(-r));
        ((float*)&o)[i] = r;
    }
    reinterpret_cast<float4*>(xct + base)[tid] = o;
}

// scan: broadcast streams (dt/xc/z) via float4 every 4 steps; B/C token-major
__global__ void __launch_bounds__(256) scan_kernel(
    const float* __restrict__ xdbl, const float* __restrict__ dtt,
    const float* __restrict__ xct,  const float* __restrict__ zt,
    const float* __restrict__ A_log, const float* __restrict__ Dp,
    float* __restrict__ yt)
{
    const int gt = blockIdx.x * blockDim.x + threadIdx.x;
    const int g = gt >> 4, s = gt & 15;
    const int b = g >> 11, d = g & 2047;

    const float Ac = -expf(A_log[d * DSTATE + s]);
    const float Dd = Dp[d];
    const size_t base = (size_t)d * NTOK + b * 1024;
    const float4* __restrict__ dtp = reinterpret_cast<const float4*>(dtt + base);
    const float4* __restrict__ xcp = reinterpret_cast<const float4*>(xct + base);
    const float4* __restrict__ zp  = reinterpret_cast<const float4*>(zt  + base);
    float* __restrict__ yp = yt + (size_t)b * 1024 * DINNER + d;
    const float* __restrict__ xd = xdbl + (size_t)(b * 1024) * XDBL_N;

    float h = 0.f;
    for (int q = 0; q < 256; q++) {
        const float4 d4 = dtp[q];
        const float4 x4 = xcp[q];
        const float4 z4 = zp[q];
        #pragma unroll
        for (int i = 0; i < 4; i++) {
            const int t = q * 4 + i;
            const float dt  = (&d4.x)[i];
            const float xc  = (&x4.x)[i];
            const float bsv = xd[t * XDBL_N + DTRANK + s];
            const float csv = xd[t * XDBL_N + DTRANK + DSTATE + s];
            const float da = __expf(dt * Ac);
            h = fmaf(da, h, dt * bsv * xc);
            float p = h * csv;
            p += __shfl_xor_sync(0xffffffffu, p, 8, 16);
            p += __shfl_xor_sync(0xffffffffu, p, 4, 16);
            p += __shfl_xor_sync(0xffffffffu, p, 2, 16);
            p += __shfl_xor_sync(0xffffffffu, p, 1, 16);
            if (s == 0) {
                const float zv = (&z4.x)[i];
                const float gate = zv / (1.f + __expf(-zv));
                yp[(size_t)t * DINNER] = (p + xc * Dd) * gate;
            }
        }
    }
}

// ---------------------------------------------------------------------------
// host
// ---------------------------------------------------------------------------
extern "C" void kernel_launch(void* const* d_in, const int* in_sizes, int n_in,
                              void* d_out, int out_size)
{
    const float* x        = (const float*)d_in[0];
    const float* ln_w     = (const float*)d_in[1];
    const float* ln_b     = (const float*)d_in[2];
    const float* in_w     = (const float*)d_in[3];
    const float* conv_w   = (const float*)d_in[4];
    const float* conv_b   = (const float*)d_in[5];
    const float* xproj_w  = (const float*)d_in[6];
    const float* dtproj_w = (const float*)d_in[7];
    const float* dtproj_b = (const float*)d_in[8];
    const float* A_log    = (const float*)d_in[9];
    const float* Dp       = (const float*)d_in[10];
    const float* out_w    = (const float*)d_in[11];
    float* out = (float*)d_out;

    float *xt, *zt, *xct, *dtt, *yt, *xdbl, *xdblp, *opart;
    cudaGetSymbolAddress((void**)&xt,    g_xt);
    cudaGetSymbolAddress((void**)&zt,    g_zt);
    cudaGetSymbolAddress((void**)&xct,   g_xct);
    cudaGetSymbolAddress((void**)&dtt,   g_dtt);
    cudaGetSymbolAddress((void**)&yt,    g_yt);
    cudaGetSymbolAddress((void**)&xdbl,  g_xdbl);
    cudaGetSymbolAddress((void**)&xdblp, g_xdbl_part);
    cudaGetSymbolAddress((void**)&opart, g_opart);

    __nv_bfloat16 *h_hi, *h_lo, *iw_hi, *iw_lo;
    cudaGetSymbolAddress((void**)&h_hi,  g_h_hi);
    cudaGetSymbolAddress((void**)&h_lo,  g_h_lo);
    cudaGetSymbolAddress((void**)&iw_hi, g_iw_hi);
    cudaGetSymbolAddress((void**)&iw_lo, g_iw_lo);

    cudaFuncSetAttribute(mm_gemm0, cudaFuncAttributeMaxDynamicSharedMemorySize,
                         MM_SMEM);
    cudaFuncSetAttribute(tf_gemm, cudaFuncAttributeMaxDynamicSharedMemorySize,
                         TF_SMEM);

    // 1. split in_w
    cvt_split<<<(2 * DINNER * DMODEL / 4) / 256, 256>>>(in_w, iw_hi, iw_lo,
                                                        2 * DINNER * DMODEL / 4);
    // 2. layernorm -> bf16 hi/lo
    ln_kernel<<<NTOK, 256>>>(x, ln_w, ln_b, h_hi, h_lo);

    // 3. in_proj (bf16-split 3-pass): M=2048, N=4096, K=1024
    mm_gemm0<<<dim3(4096 / 128, NTOK / 128), 256, MM_SMEM>>>(
        h_hi, h_lo, DMODEL, iw_hi, iw_lo, DMODEL, DMODEL / KC, xt, zt);

    // 4. depthwise conv + silu
    conv_kernel<<<DINNER * 2, 256>>>(xt, conv_w, conv_b, xct);

    // 5. x_proj (fp32 split-K)
    gemm_k<0, true, 4><<<dim3(2, NTOK / BM, SPLITK), 256>>>(
        xct, NTOK, xproj_w, xdblp, nullptr, nullptr, nullptr,
        NTOK, XDBL_N, DINNER, DINNER / SPLITK);
    reduce_k<<<(NTOK * XDBL_N + 255) / 256, 256>>>(xdblp, xdbl, NTOK * XDBL_N);

    // 6. dt = softplus(...) (fp32)
    gemm_k<2, false, 8><<<dim3(DINNER / 128, NTOK / BM, 1), 256>>>(
        xdbl, XDBL_N, dtproj_w, dtt, nullptr, dtproj_b, nullptr,
        NTOK, DINNER, DTRANK, DTRANK);

    // 7. selective scan -> yt fp32 token-major
    scan_kernel<<<(2 * DINNER * DSTATE) / 256, 256>>>(
        xdbl, dtt, xct, zt, A_log, Dp, yt);

    // 8. out_proj (tf32 single-pass, split-K=2): M=2048, N=1024, K=2048
    tf_gemm<<<dim3(DMODEL / 128, NTOK / 128, 2), 256, TF_SMEM>>>(
        yt, DINNER, out_w, DINNER, (DINNER / KC) / 2, opart);

    // 9. reduce partials + residual
    add_out<<<(NTOK * DMODEL / 4) / 256, 256>>>(opart, x, out);
}

// round 16
// speedup vs baseline: 1.4736x; 1.0345x over previous
#include <cuda_runtime.h>
#include <cuda_bf16.h>
#include <cstdint>

// ---------------------------------------------------------------------------
// MambaBlock on GB300 (plain sm_103 -> mma.sync path).  R14 numerics (729us)
// + 4-stage (Kc=16) cp.async pipeline with ONE __syncthreads per stage.
// Alignment fix vs R15: bf16 stage row stride = 48B (16B multiple).
// ---------------------------------------------------------------------------

#define NTOK    2048
#define DMODEL  1024
#define DINNER  2048
#define DSTATE  16
#define DTRANK  64
#define XDBL_N  96
#define SPLITK  8

__device__ float g_xt  [DINNER * NTOK];
__device__ float g_zt  [DINNER * NTOK];
__device__ float g_xct [DINNER * NTOK];
__device__ float g_dtt [DINNER * NTOK];
__device__ float g_yt  [NTOK * DINNER];        // token-major fp32
__device__ float g_xdbl[NTOK * XDBL_N];
__device__ float g_xdbl_part[SPLITK * NTOK * XDBL_N];
__device__ float g_opart[2 * NTOK * DMODEL];   // out_proj split-K partials

// pre-split bf16 hi/lo (in_proj only)
__device__ __nv_bfloat16 g_h_hi [NTOK * DMODEL];
__device__ __nv_bfloat16 g_h_lo [NTOK * DMODEL];
__device__ __nv_bfloat16 g_iw_hi[2 * DINNER * DMODEL];
__device__ __nv_bfloat16 g_iw_lo[2 * DINNER * DMODEL];

// =========================== helpers =======================================
__device__ __forceinline__ uint32_t smem_u32(const void* p) {
    uint32_t a;
    asm("{ .reg .u64 t; cvta.to.shared.u64 t, %1; cvt.u32.u64 %0, t; }"
        : "=r"(a) : "l"(p));
    return a;
}

__device__ __forceinline__ void ldm_x4(uint32_t* r, uint32_t addr) {
    asm volatile("ldmatrix.sync.aligned.m8n8.x4.shared.b16 {%0,%1,%2,%3}, [%4];"
        : "=r"(r[0]), "=r"(r[1]), "=r"(r[2]), "=r"(r[3]) : "r"(addr));
}

__device__ __forceinline__ void mma_bf16(float* c, const uint32_t* a,
                                         const uint32_t* b) {
    asm volatile(
        "mma.sync.aligned.m16n8k16.row.col.f32.bf16.bf16.f32 "
        "{%0,%1,%2,%3}, {%4,%5,%6,%7}, {%8,%9}, {%0,%1,%2,%3};"
        : "+f"(c[0]), "+f"(c[1]), "+f"(c[2]), "+f"(c[3])
        : "r"(a[0]), "r"(a[1]), "r"(a[2]), "r"(a[3]), "r"(b[0]), "r"(b[1]));
}

__device__ __forceinline__ void mma_tf32(float* c, const uint32_t* a,
                                         const uint32_t* b) {
    asm volatile(
        "mma.sync.aligned.m16n8k8.row.col.f32.tf32.tf32.f32 "
        "{%0,%1,%2,%3}, {%4,%5,%6,%7}, {%8,%9}, {%0,%1,%2,%3};"
        : "+f"(c[0]), "+f"(c[1]), "+f"(c[2]), "+f"(c[3])
        : "r"(a[0]), "r"(a[1]), "r"(a[2]), "r"(a[3]), "r"(b[0]), "r"(b[1]));
}

__device__ __forceinline__ uint32_t to_tf32(float x) {
    uint32_t u;
    asm("cvt.rna.tf32.f32 %0, %1;" : "=r"(u) : "f"(x));
    return u;
}

#define CP16(dst, src) \
    asm volatile("cp.async.cg.shared.global [%0], [%1], 16;" \
                 :: "r"(dst), "l"(src))
#define CP_COMMIT() asm volatile("cp.async.commit_group;" ::: "memory")

// fp32 -> bf16 hi/lo split (elementwise)
__global__ void __launch_bounds__(256) cvt_split(
    const float* __restrict__ src, __nv_bfloat16* __restrict__ hi,
    __nv_bfloat16* __restrict__ lo, int n4)
{
    const int i = blockIdx.x * 256 + threadIdx.x;
    if (i >= n4) return;
    const float4 v = reinterpret_cast<const float4*>(src)[i];
    __nv_bfloat162 h0 = __floats2bfloat162_rn(v.x, v.y);
    __nv_bfloat162 h1 = __floats2bfloat162_rn(v.z, v.w);
    __nv_bfloat162 l0 = __floats2bfloat162_rn(v.x - __bfloat162float(h0.x),
                                              v.y - __bfloat162float(h0.y));
    __nv_bfloat162 l1 = __floats2bfloat162_rn(v.z - __bfloat162float(h1.x),
                                              v.w - __bfloat162float(h1.y));
    reinterpret_cast<__nv_bfloat162*>(hi)[2*i]   = h0;
    reinterpret_cast<__nv_bfloat162*>(hi)[2*i+1] = h1;
    reinterpret_cast<__nv_bfloat162*>(lo)[2*i]   = l0;
    reinterpret_cast<__nv_bfloat162*>(lo)[2*i+1] = l1;
}

// ---------------------------------------------------------------------------
// bf16-split tensor GEMM (in_proj): CTA 128x128, 256 threads, 8 warps =
// 2(m) x 4(n), warp 64x32.  4-stage Kc=16 cp.async pipeline, 1 sync/stage.
// Stage (24576B): Ahi[128] rows of 48B @0, Alo @6144, Bhi @12288, Blo @18432.
// 48B row stride: data 32B (16 bf16) + 16B pad; 16B-aligned everywhere.
// Channel-major store via smem transpose.
// ---------------------------------------------------------------------------
#define KC16   16
#define STG4   24576
#define O_ALO  6144
#define O_BHI  12288
#define O_BLO  18432
#define MM_SMEM 98304

__global__ void __launch_bounds__(256, 2) mm_gemm0(
    const __nv_bfloat16* __restrict__ Ahi, const __nv_bfloat16* __restrict__ Alo,
    int lda,
    const __nv_bfloat16* __restrict__ Bhi, const __nv_bfloat16* __restrict__ Blo,
    int ldb, int nchunk,
    float* __restrict__ out0, float* __restrict__ out1)
{
    extern __shared__ char smem_dyn[];
    const uint32_t sbase = smem_u32(smem_dyn);
    const int tid  = threadIdx.x;
    const int lane = tid & 31;
    const int w    = tid >> 5;
    const int wm   = w >> 2;
    const int wn   = w & 3;
    const int n0   = blockIdx.x * 128;
    const int m0   = blockIdx.y * 128;

    const int lrow  = tid >> 1;            // 0..127
    const int lhalf = (tid & 1) * 8;       // bf16 elements (0 or 8)

    const int a_row  = wm * 64 + (lane & 15);
    const int a_coff = ((lane & 16) ? 16 : 0);
    const int b_row  = wn * 32 + ((lane >> 4) & 1) * 8 + (lane & 7);
    const int b_coff = ((lane & 8) ? 16 : 0);

    float acc[4][4][4];
    #pragma unroll
    for (int i = 0; i < 4; i++)
        #pragma unroll
        for (int j = 0; j < 4; j++)
            #pragma unroll
            for (int p = 0; p < 4; p++) acc[i][j][p] = 0.f;

#define ISSUE(c_, buf_) do {                                                    \
    const int kc0 = (c_) * KC16;                                                \
    const uint32_t sd = sbase + (buf_) * STG4 + lrow * 48 + lhalf * 2;          \
    CP16(sd,          Ahi + (size_t)(m0 + lrow) * lda + kc0 + lhalf);           \
    CP16(sd + O_ALO,  Alo + (size_t)(m0 + lrow) * lda + kc0 + lhalf);           \
    CP16(sd + O_BHI,  Bhi + (size_t)(n0 + lrow) * ldb + kc0 + lhalf);           \
    CP16(sd + O_BLO,  Blo + (size_t)(n0 + lrow) * ldb + kc0 + lhalf);           \
    CP_COMMIT();                                                                \
    } while (0)

#define COMPUTE(buf_) do {                                                      \
    const uint32_t sa = sbase + (buf_) * STG4;                                  \
    uint32_t Ah[4][4], Al[4][4], Bh[2][4], Bl[2][4];                            \
    _Pragma("unroll")                                                           \
    for (int mf = 0; mf < 4; mf++) {                                            \
        const uint32_t ar = sa + (a_row + mf * 16) * 48 + a_coff;               \
        ldm_x4(Ah[mf], ar);                                                     \
        ldm_x4(Al[mf], ar + O_ALO);                                             \
    }                                                                           \
    _Pragma("unroll")                                                           \
    for (int np = 0; np < 2; np++) {                                            \
        const uint32_t br = sa + O_BHI + (b_row + np * 16) * 48 + b_coff;       \
        ldm_x4(Bh[np], br);                                                     \
        ldm_x4(Bl[np], br + (O_BLO - O_BHI));                                   \
    }                                                                           \
    _Pragma("unroll")                                                           \
    for (int mf = 0; mf < 4; mf++)                                              \
        _Pragma("unroll")                                                       \
        for (int nf = 0; nf < 4; nf++) {                                        \
            const uint32_t* bh = &Bh[nf >> 1][(nf & 1) * 2];                    \
            const uint32_t* bl = &Bl[nf >> 1][(nf & 1) * 2];                    \
            mma_bf16(acc[mf][nf], Ah[mf], bh);                                  \
            mma_bf16(acc[mf][nf], Ah[mf], bl);                                  \
            mma_bf16(acc[mf][nf], Al[mf], bh);                                  \
        }                                                                       \
    } while (0)

    ISSUE(0, 0); ISSUE(1, 1); ISSUE(2, 2);
    for (int c = 0; c < nchunk; c++) {
        asm volatile("cp.async.wait_group 2;" ::: "memory");
        __syncthreads();
        COMPUTE(c & 3);
        if (c + 3 < nchunk) ISSUE(c + 3, (c + 3) & 3);
        else CP_COMMIT();
    }
    asm volatile("cp.async.wait_group 0;" ::: "memory");
    __syncthreads();

#undef ISSUE
#undef COMPUTE

    const int rg = lane >> 2;
    const int cp = (lane & 3) * 2;

    float* T = reinterpret_cast<float*>(smem_dyn);
    #pragma unroll
    for (int mf = 0; mf < 4; mf++)
        #pragma unroll
        for (int nf = 0; nf < 4; nf++) {
            const int m = wm * 64 + mf * 16 + rg;
            const int n = wn * 32 + nf * 8 + cp;
            T[(n    ) * 132 + m    ] = acc[mf][nf][0];
            T[(n + 1) * 132 + m    ] = acc[mf][nf][1];
            T[(n    ) * 132 + m + 8] = acc[mf][nf][2];
            T[(n + 1) * 132 + m + 8] = acc[mf][nf][3];
        }
    __syncthreads();
    float* ob; int nc0;
    if (n0 < 2048) { ob = out0; nc0 = n0; }
    else           { ob = out1; nc0 = n0 - 2048; }
    const int n  = tid >> 1;
    const int mh = (tid & 1) * 64;
    const float4* src = reinterpret_cast<const float4*>(&T[n * 132 + mh]);
    float4* dst = reinterpret_cast<float4*>(
        ob + (size_t)(nc0 + n) * NTOK + m0 + mh);
    #pragma unroll
    for (int j = 0; j < 16; j++) dst[j] = src[j];
}

// ---------------------------------------------------------------------------
// tf32 single-pass GEMM (out_proj), 4-stage Kc=16 pipeline, 1 sync/stage.
// Stage (20480B): As[128][20]f32 @0 (10240B), Bs @10240.  Row stride 20 f32
// (80B, 16B multiple).  Split-K partial out.
// ---------------------------------------------------------------------------
#define TSTG   20480
#define T_B    10240
#define TF_SMEM 81920

__global__ void __launch_bounds__(256, 2) tf_gemm(
    const float* __restrict__ A, int lda,
    const float* __restrict__ B, int ldb, int nchunk,
    float* __restrict__ out0)
{
    extern __shared__ char smem_dyn[];
    float* Sf = reinterpret_cast<float*>(smem_dyn);
    const uint32_t sbase = smem_u32(smem_dyn);
    const int tid  = threadIdx.x;
    const int lane = tid & 31;
    const int w    = tid >> 5;
    const int wm   = w >> 2;
    const int wn   = w & 3;
    const int n0   = blockIdx.x * 128;
    const int m0   = blockIdx.y * 128;
    const int kbase = blockIdx.z * nchunk;

    const int lrow  = tid >> 1;            // 0..127
    const int lhalf = (tid & 1) * 8;       // floats (0 or 8)

    const int g = lane >> 2;               // 0..7
    const int t = lane & 3;                // 0..3

    float acc[4][4][4];
    #pragma unroll
    for (int i = 0; i < 4; i++)
        #pragma unroll
        for (int j = 0; j < 4; j++)
            #pragma unroll
            for (int p = 0; p < 4; p++) acc[i][j][p] = 0.f;

#define TISSUE(c_, buf_) do {                                                   \
    const int kc0 = (c_) * KC16;                                                \
    const uint32_t sd = sbase + (buf_) * TSTG + (lrow * 20 + lhalf) * 4;        \
    const float* ag = A + (size_t)(m0 + lrow) * lda + kc0 + lhalf;              \
    const float* bg = B + (size_t)(n0 + lrow) * ldb + kc0 + lhalf;              \
    CP16(sd,           ag);  CP16(sd + 16,       ag + 4);                       \
    CP16(sd + T_B,     bg);  CP16(sd + T_B + 16, bg + 4);                       \
    CP_COMMIT();                                                                \
    } while (0)

#define TCOMPUTE(buf_) do {                                                     \
    float* As = Sf + (buf_) * (TSTG / 4);                                       \
    float* Bs = As + (T_B / 4);                                                 \
    _Pragma("unroll")                                                           \
    for (int ks = 0; ks < 2; ks++) {                                            \
        uint32_t Af[4][4], Bf[4][2];                                            \
        _Pragma("unroll")                                                       \
        for (int mf = 0; mf < 4; mf++) {                                        \
            const int r = wm * 64 + mf * 16 + g;                                \
            const int c = ks * 8 + t;                                           \
            Af[mf][0] = to_tf32(As[(r    ) * 20 + c    ]);                      \
            Af[mf][1] = to_tf32(As[(r + 8) * 20 + c    ]);                      \
            Af[mf][2] = to_tf32(As[(r    ) * 20 + c + 4]);                      \
            Af[mf][3] = to_tf32(As[(r + 8) * 20 + c + 4]);                      \
        }                                                                       \
        _Pragma("unroll")                                                       \
        for (int nf = 0; nf < 4; nf++) {                                        \
            const int r = wn * 32 + nf * 8 + g;                                 \
            const int c = ks * 8 + t;                                           \
            Bf[nf][0] = to_tf32(Bs[r * 20 + c    ]);                            \
            Bf[nf][1] = to_tf32(Bs[r * 20 + c + 4]);                            \
        }                                                                       \
        _Pragma("unroll")                                                       \
        for (int mf = 0; mf < 4; mf++)                                          \
            _Pragma("unroll")                                                   \
            for (int nf = 0; nf < 4; nf++)                                      \
                mma_tf32(acc[mf][nf], Af[mf], Bf[nf]);                          \
    } } while (0)

    TISSUE(kbase, 0); TISSUE(kbase + 1, 1); TISSUE(kbase + 2, 2);
    for (int c = 0; c < nchunk; c++) {
        asm volatile("cp.async.wait_group 2;" ::: "memory");
        __syncthreads();
        TCOMPUTE(c & 3);
        if (c + 3 < nchunk) TISSUE(kbase + c + 3, (c + 3) & 3);
        else CP_COMMIT();
    }

#undef TISSUE
#undef TCOMPUTE

    const int rg = lane >> 2;
    const int cp = (lane & 3) * 2;
    float* part = out0 + (size_t)blockIdx.z * NTOK * DMODEL;
    #pragma unroll
    for (int mf = 0; mf < 4; mf++)
        #pragma unroll
        for (int nf = 0; nf < 4; nf++) {
            const int m = m0 + wm * 64 + mf * 16 + rg;
            const int n = n0 + wn * 32 + nf * 8 + cp;
            *reinterpret_cast<float2*>(part + (size_t)m * DMODEL + n) =
                make_float2(acc[mf][nf][0], acc[mf][nf][1]);
            *reinterpret_cast<float2*>(part + (size_t)(m + 8) * DMODEL + n) =
                make_float2(acc[mf][nf][2], acc[mf][nf][3]);
        }
}

// out = part0 + part1 + x   (split-K reduce + residual)
__global__ void __launch_bounds__(256) add_out(
    const float* __restrict__ part, const float* __restrict__ x,
    float* __restrict__ out)
{
    const int i = blockIdx.x * 256 + threadIdx.x;
    const float4 a = reinterpret_cast<const float4*>(part)[i];
    const float4 b = reinterpret_cast<const float4*>(part + NTOK * DMODEL)[i];
    const float4 c = reinterpret_cast<const float4*>(x)[i];
    float4 o;
    o.x = a.x + b.x + c.x; o.y = a.y + b.y + c.y;
    o.z = a.z + b.z + c.z; o.w = a.w + b.w + c.w;
    reinterpret_cast<float4*>(out)[i] = o;
}

// ============================ fp32 kernels =================================
__device__ __forceinline__ unsigned long long dup2(float x) {
    unsigned long long r;
    asm("mov.b64 %0, {%1, %1};" : "=l"(r) : "f"(x));
    return r;
}
__device__ __forceinline__ void fma2(unsigned long long& d,
                                     unsigned long long a,
                                     unsigned long long b) {
    asm("fma.rn.f32x2 %0, %1, %2, %0;" : "+l"(d) : "l"(a), "l"(b));
}

// LayerNorm -> bf16 hi/lo
__global__ void __launch_bounds__(256) ln_kernel(
    const float* __restrict__ x, const float* __restrict__ w,
    const float* __restrict__ b,
    __nv_bfloat16* __restrict__ hi, __nv_bfloat16* __restrict__ lo)
{
    const int tkn = blockIdx.x;
    const float4 v = reinterpret_cast<const float4*>(x + (size_t)tkn * DMODEL)[threadIdx.x];
    float s  = v.x + v.y + v.z + v.w;
    float sq = v.x*v.x + v.y*v.y + v.z*v.z + v.w*v.w;

    __shared__ float sa[8], sb2[8];
    int lane = threadIdx.x & 31, wrp = threadIdx.x >> 5;
    #pragma unroll
    for (int o = 16; o; o >>= 1) {
        s  += __shfl_down_sync(0xffffffffu, s,  o);
        sq += __shfl_down_sync(0xffffffffu, sq, o);
    }
    if (lane == 0) { sa[wrp] = s; sb2[wrp] = sq; }
    __syncthreads();
    if (wrp == 0) {
        s  = (lane < 8) ? sa[lane] : 0.f;
        sq = (lane < 8) ? sb2[lane] : 0.f;
        #pragma unroll
        for (int o = 4; o; o >>= 1) {
            s  += __shfl_down_sync(0xffffffffu, s,  o);
            sq += __shfl_down_sync(0xffffffffu, sq, o);
        }
        if (lane == 0) { sa[0] = s; sb2[0] = sq; }
    }
    __syncthreads();
    const float mu  = sa[0] * (1.f / DMODEL);
    const float var = sb2[0] * (1.f / DMODEL) - mu * mu;
    const float inv = rsqrtf(var + 1e-5f);

    const float4 wv = reinterpret_cast<const float4*>(w)[threadIdx.x];
    const float4 bv = reinterpret_cast<const float4*>(b)[threadIdx.x];
    float4 o4;
    o4.x = (v.x - mu) * inv * wv.x + bv.x;
    o4.y = (v.y - mu) * inv * wv.y + bv.y;
    o4.z = (v.z - mu) * inv * wv.z + bv.z;
    o4.w = (v.w - mu) * inv * wv.w + bv.w;

    __nv_bfloat162 h0 = __floats2bfloat162_rn(o4.x, o4.y);
    __nv_bfloat162 h1 = __floats2bfloat162_rn(o4.z, o4.w);
    __nv_bfloat162 l0 = __floats2bfloat162_rn(o4.x - __bfloat162float(h0.x),
                                              o4.y - __bfloat162float(h0.y));
    __nv_bfloat162 l1 = __floats2bfloat162_rn(o4.z - __bfloat162float(h1.x),
                                              o4.w - __bfloat162float(h1.y));
    const size_t base2 = ((size_t)tkn * DMODEL) / 2 + threadIdx.x * 2;
    reinterpret_cast<__nv_bfloat162*>(hi)[base2]     = h0;
    reinterpret_cast<__nv_bfloat162*>(hi)[base2 + 1] = h1;
    reinterpret_cast<__nv_bfloat162*>(lo)[base2]     = l0;
    reinterpret_cast<__nv_bfloat162*>(lo)[base2 + 1] = l1;
}

#define BM  128
#define BKT 16
#define APAD 4

template<int MODE, bool ACOL, int TN>
__global__ void __launch_bounds__(256) gemm_k(
    const float* __restrict__ A, int lda, const float* __restrict__ B,
    float* __restrict__ C, float* __restrict__ C2,
    const float* __restrict__ bias, const float* __restrict__ resid,
    int M, int N, int K, int kSplitLen)
{
    constexpr int BN = TN * 16;
    __shared__ __align__(16) float As[2][BKT][BM + APAD];
    __shared__ __align__(16) float Bs[2][BKT][BN];

    const int tid = threadIdx.x;
    const int n0 = blockIdx.x * BN;
    const int m0 = blockIdx.y * BM;
    const int kBase = blockIdx.z * kSplitLen;
    const int nT = kSplitLen / BKT;
    const int tm = tid >> 4, tn = tid & 15;

    unsigned long long acc[TN][4];
    #pragma unroll
    for (int j = 0; j < TN; j++)
        #pragma unroll
        for (int p = 0; p < 4; p++) acc[j][p] = 0ull;

    float4 ar0, ar1, br0, br1;

#define LOAD_A(k0_) do {                                                        \
    if (ACOL) {                                                                 \
        const int m4 = tid & 31, kr = tid >> 5;                                 \
        ar0 = *(const float4*)(A + (size_t)((k0_) + kr)     * lda + m0 + m4*4); \
        ar1 = *(const float4*)(A + (size_t)((k0_) + kr + 8) * lda + m0 + m4*4); \
    } else {                                                                    \
        const int rr = tid >> 2, kq = tid & 3;                                  \
        ar0 = *(const float4*)(A + (size_t)(m0 + rr)      * lda + (k0_) + kq*4);\
        ar1 = *(const float4*)(A + (size_t)(m0 + rr + 64) * lda + (k0_) + kq*4);\
    } } while (0)

#define LOAD_B(k0_) do {                                                        \
    if (TN == 8) {                                                              \
        const int nr = tid >> 1, kq = tid & 1;                                  \
        if (n0 + nr < N) {                                                      \
            const float* bp = B + (size_t)(n0 + nr) * K + (k0_) + kq * 8;       \
            br0 = *(const float4*)(bp);                                         \
            br1 = *(const float4*)(bp + 4);                                     \
        } else { br0 = make_float4(0,0,0,0); br1 = br0; }                       \
    } else {                                                                    \
        const int nr = tid >> 2, kq = tid & 3;                                  \
        br0 = (n0 + nr < N)                                                     \
            ? *(const float4*)(B + (size_t)(n0 + nr) * K + (k0_) + kq*4)        \
            : make_float4(0,0,0,0);                                             \
    } } while (0)

#define STORE_A(st_) do {                                                       \
    if (ACOL) {                                                                 \
        const int m4 = tid & 31, kr = tid >> 5;                                 \
        *(float4*)&As[st_][kr  ][m4*4] = ar0;                                   \
        *(float4*)&As[st_][kr+8][m4*4] = ar1;                                   \
    } else {                                                                    \
        const int rr = tid >> 2, kq = tid & 3;                                  \
        As[st_][kq*4+0][rr]    = ar0.x; As[st_][kq*4+1][rr]    = ar0.y;         \
        As[st_][kq*4+2][rr]    = ar0.z; As[st_][kq*4+3][rr]    = ar0.w;         \
        As[st_][kq*4+0][rr+64] = ar1.x; As[st_][kq*4+1][rr+64] = ar1.y;         \
        As[st_][kq*4+2][rr+64] = ar1.z; As[st_][kq*4+3][rr+64] = ar1.w;         \
    } } while (0)

#define STORE_B(st_) do {                                                       \
    if (TN == 8) {                                                              \
        const int nr = tid >> 1, kq = tid & 1;                                  \
        Bs[st_][kq*8+0][nr] = br0.x; Bs[st_][kq*8+1][nr] = br0.y;               \
        Bs[st_][kq*8+2][nr] = br0.z; Bs[st_][kq*8+3][nr] = br0.w;               \
        Bs[st_][kq*8+4][nr] = br1.x; Bs[st_][kq*8+5][nr] = br1.y;               \
        Bs[st_][kq*8+6][nr] = br1.z; Bs[st_][kq*8+7][nr] = br1.w;               \
    } else {                                                                    \
        const int nr = tid >> 2, kq = tid & 3;                                  \
        Bs[st_][kq*4+0][nr] = br0.x; Bs[st_][kq*4+1][nr] = br0.y;               \
        Bs[st_][kq*4+2][nr] = br0.z; Bs[st_][kq*4+3][nr] = br0.w;               \
    } } while (0)

#define COMPUTE(st_) do {                                                       \
    _Pragma("unroll")                                                           \
    for (int kk = 0; kk < BKT; kk++) {                                          \
        const float* arow = &As[st_][kk][tm * 8];                               \
        ulonglong2 a01 = *(const ulonglong2*)(arow);                            \
        ulonglong2 a23 = *(const ulonglong2*)(arow + 4);                        \
        unsigned long long apk[4] = {a01.x, a01.y, a23.x, a23.y};               \
        float bv[TN];                                                           \
        *(float4*)&bv[0] = *(const float4*)&Bs[st_][kk][tn * TN];               \
        if (TN == 8)                                                            \
            *(float4*)&bv[4] = *(const float4*)&Bs[st_][kk][tn * TN + 4];       \
        _Pragma("unroll")                                                       \
        for (int j = 0; j < TN; j++) {                                          \
            unsigned long long bd = dup2(bv[j]);                                \
            _Pragma("unroll")                                                   \
            for (int p = 0; p < 4; p++) fma2(acc[j][p], apk[p], bd);            \
        }                                                                       \
    } } while (0)

    int k0 = kBase;
    LOAD_A(k0); LOAD_B(k0);
    STORE_A(0); STORE_B(0);
    __syncthreads();
    int st = 0;
    for (int t2 = 0; t2 < nT; t2++) {
        const bool more = (t2 + 1 < nT);
        if (more) { LOAD_A(k0 + BKT); LOAD_B(k0 + BKT); }
        COMPUTE(st);
        if (more) {
            STORE_A(st ^ 1); STORE_B(st ^ 1);
            __syncthreads();
            st ^= 1; k0 += BKT;
        }
    }

#undef LOAD_A
#undef LOAD_B
#undef STORE_A
#undef STORE_B
#undef COMPUTE

    #pragma unroll
    for (int j = 0; j < TN; j++) {
        const int n = n0 + tn * TN + j;
        if (n >= N) continue;
        #pragma unroll
        for (int p = 0; p < 4; p++) {
            const int m = m0 + tm * 8 + 2 * p;
            float2 v = *reinterpret_cast<float2*>(&acc[j][p]);
            if (MODE == 0) {
                float* dst = C + (size_t)blockIdx.z * M * N + (size_t)m * N + n;
                dst[0] = v.x; dst[N] = v.y;
            } else if (MODE == 2) {
                const float bx = bias[n];
                float a0 = v.x + bx, a1 = v.y + bx;
                a0 = (a0 > 20.f) ? a0 : log1pf(expf(a0));
                a1 = (a1 > 20.f) ? a1 : log1pf(expf(a1));
                *reinterpret_cast<float2*>(C + (size_t)n * M + m) = make_float2(a0, a1);
            }
        }
    }
}

__global__ void __launch_bounds__(256) reduce_k(
    const float* __restrict__ part, float* __restrict__ out, int n)
{
    const int i = blockIdx.x * 256 + threadIdx.x;
    if (i < n) {
        float s = 0.f;
        #pragma unroll
        for (int z = 0; z < SPLITK; z++) s += part[(size_t)z * n + i];
        out[i] = s;
    }
}

__global__ void __launch_bounds__(256) conv_kernel(
    const float* __restrict__ xt, const float* __restrict__ cw,
    const float* __restrict__ cb, float* __restrict__ xct)
{
    const int row = blockIdx.x;
    const int d = row >> 1, b = row & 1;
    const size_t base = (size_t)d * NTOK + b * 1024;

    __shared__ float s[1024 + 3];
    const int tid = threadIdx.x;
    const float4 v = reinterpret_cast<const float4*>(xt + base)[tid];
    s[3 + tid*4 + 0] = v.x; s[3 + tid*4 + 1] = v.y;
    s[3 + tid*4 + 2] = v.z; s[3 + tid*4 + 3] = v.w;
    if (tid == 0) { s[0] = 0.f; s[1] = 0.f; s[2] = 0.f; }
    __syncthreads();

    const float w0 = cw[d*4+0], w1 = cw[d*4+1], w2 = cw[d*4+2], w3 = cw[d*4+3];
    const float bs = cb[d];
    float4 o;
    #pragma unroll
    for (int i = 0; i < 4; i++) {
        const int l = tid * 4 + i;
        float r = bs + w0*s[l] + w1*s[l+1] + w2*s[l+2] + w3*s[l+3];
        r = r / (1.f + __expf(-r));
        ((float*)&o)[i] = r;
    }
    reinterpret_cast<float4*>(xct + base)[tid] = o;
}

// scan: broadcast streams (dt/xc/z) via float4 every 4 steps; B/C token-major
__global__ void __launch_bounds__(256) scan_kernel(
    const float* __restrict__ xdbl, const float* __restrict__ dtt,
    const float* __restrict__ xct,  const float* __restrict__ zt,
    const float* __restrict__ A_log, const float* __restrict__ Dp,
    float* __restrict__ yt)
{
    const int gt = blockIdx.x * blockDim.x + threadIdx.x;
    const int g = gt >> 4, s = gt & 15;
    const int b = g >> 11, d = g & 2047;

    const float Ac = -expf(A_log[d * DSTATE + s]);
    const float Dd = Dp[d];
    const size_t base = (size_t)d * NTOK + b * 1024;
    const float4* __restrict__ dtp = reinterpret_cast<const float4*>(dtt + base);
    const float4* __restrict__ xcp = reinterpret_cast<const float4*>(xct + base);
    const float4* __restrict__ zp  = reinterpret_cast<const float4*>(zt  + base);
    float* __restrict__ yp = yt + (size_t)b * 1024 * DINNER + d;
    const float* __restrict__ xd = xdbl + (size_t)(b * 1024) * XDBL_N;

    float h = 0.f;
    for (int q = 0; q < 256; q++) {
        const float4 d4 = dtp[q];
        const float4 x4 = xcp[q];
        const float4 z4 = zp[q];
        #pragma unroll
        for (int i = 0; i < 4; i++) {
            const int t = q * 4 + i;
            const float dt  = (&d4.x)[i];
            const float xc  = (&x4.x)[i];
            const float bsv = xd[t * XDBL_N + DTRANK + s];
            const float csv = xd[t * XDBL_N + DTRANK + DSTATE + s];
            const float da = __expf(dt * Ac);
            h = fmaf(da, h, dt * bsv * xc);
            float p = h * csv;
            p += __shfl_xor_sync(0xffffffffu, p, 8, 16);
            p += __shfl_xor_sync(0xffffffffu, p, 4, 16);
            p += __shfl_xor_sync(0xffffffffu, p, 2, 16);
            p += __shfl_xor_sync(0xffffffffu, p, 1, 16);
            if (s == 0) {
                const float zv = (&z4.x)[i];
                const float gate = zv / (1.f + __expf(-zv));
                yp[(size_t)t * DINNER] = (p + xc * Dd) * gate;
            }
        }
    }
}

// ---------------------------------------------------------------------------
// host
// ---------------------------------------------------------------------------
extern "C" void kernel_launch(void* const* d_in, const int* in_sizes, int n_in,
                              void* d_out, int out_size)
{
    const float* x        = (const float*)d_in[0];
    const float* ln_w     = (const float*)d_in[1];
    const float* ln_b     = (const float*)d_in[2];
    const float* in_w     = (const float*)d_in[3];
    const float* conv_w   = (const float*)d_in[4];
    const float* conv_b   = (const float*)d_in[5];
    const float* xproj_w  = (const float*)d_in[6];
    const float* dtproj_w = (const float*)d_in[7];
    const float* dtproj_b = (const float*)d_in[8];
    const float* A_log    = (const float*)d_in[9];
    const float* Dp       = (const float*)d_in[10];
    const float* out_w    = (const float*)d_in[11];
    float* out = (float*)d_out;

    float *xt, *zt, *xct, *dtt, *yt, *xdbl, *xdblp, *opart;
    cudaGetSymbolAddress((void**)&xt,    g_xt);
    cudaGetSymbolAddress((void**)&zt,    g_zt);
    cudaGetSymbolAddress((void**)&xct,   g_xct);
    cudaGetSymbolAddress((void**)&dtt,   g_dtt);
    cudaGetSymbolAddress((void**)&yt,    g_yt);
    cudaGetSymbolAddress((void**)&xdbl,  g_xdbl);
    cudaGetSymbolAddress((void**)&xdblp, g_xdbl_part);
    cudaGetSymbolAddress((void**)&opart, g_opart);

    __nv_bfloat16 *h_hi, *h_lo, *iw_hi, *iw_lo;
    cudaGetSymbolAddress((void**)&h_hi,  g_h_hi);
    cudaGetSymbolAddress((void**)&h_lo,  g_h_lo);
    cudaGetSymbolAddress((void**)&iw_hi, g_iw_hi);
    cudaGetSymbolAddress((void**)&iw_lo, g_iw_lo);

    cudaFuncSetAttribute(mm_gemm0, cudaFuncAttributeMaxDynamicSharedMemorySize,
                         MM_SMEM);
    cudaFuncSetAttribute(tf_gemm, cudaFuncAttributeMaxDynamicSharedMemorySize,
                         TF_SMEM);

    // 1-2. split in_w (two half launches so mm0 sits in profiled slot 4)
    const int iwq = 2 * DINNER * DMODEL / 4;   // float4 count
    cvt_split<<<(iwq / 2) / 256, 256>>>(in_w, iw_hi, iw_lo, iwq / 2);
    cvt_split<<<(iwq / 2) / 256, 256>>>(in_w + 4 * (iwq / 2),
                                        iw_hi + 4 * (iwq / 2),
                                        iw_lo + 4 * (iwq / 2), iwq / 2);
    // 3. layernorm -> bf16 hi/lo
    ln_kernel<<<NTOK, 256>>>(x, ln_w, ln_b, h_hi, h_lo);

    // 4. in_proj (bf16-split, 4-stage pipeline): M=2048, N=4096, K=1024
    mm_gemm0<<<dim3(4096 / 128, NTOK / 128), 256, MM_SMEM>>>(
        h_hi, h_lo, DMODEL, iw_hi, iw_lo, DMODEL, DMODEL / KC16, xt, zt);

    // 5. depthwise conv + silu
    conv_kernel<<<DINNER * 2, 256>>>(xt, conv_w, conv_b, xct);

    // 6. x_proj (fp32 split-K)
    gemm_k<0, true, 4><<<dim3(2, NTOK / BM, SPLITK), 256>>>(
        xct, NTOK, xproj_w, xdblp, nullptr, nullptr, nullptr,
        NTOK, XDBL_N, DINNER, DINNER / SPLITK);
    reduce_k<<<(NTOK * XDBL_N + 255) / 256, 256>>>(xdblp, xdbl, NTOK * XDBL_N);

    // 7. dt = softplus(...) (fp32)
    gemm_k<2, false, 8><<<dim3(DINNER / 128, NTOK / BM, 1), 256>>>(
        xdbl, XDBL_N, dtproj_w, dtt, nullptr, dtproj_b, nullptr,
        NTOK, DINNER, DTRANK, DTRANK);

    // 8. selective scan -> yt fp32 token-major
    scan_kernel<<<(2 * DINNER * DSTATE) / 256, 256>>>(
        xdbl, dtt, xct, zt, A_log, Dp, yt);

    // 9. out_proj (tf32, 4-stage pipeline, split-K=2): M=2048, N=1024, K=2048
    tf_gemm<<<dim3(DMODEL / 128, NTOK / 128, 2), 256, TF_SMEM>>>(
        yt, DINNER, out_w, DINNER, (DINNER / KC16) / 2, opart);

    // 10. reduce partials + residual
    add_out<<<(NTOK * DMODEL / 4) / 256, 256>>>(opart, x, out);
}